// round 1
// baseline (speedup 1.0000x reference)
#include <cuda_runtime.h>
#include <math.h>

// Problem constants (fixed by the reference)
#define N_TOK  8192
#define D_INF  1024
#define D_HIDF 4096
#define D_OUTF 1024
#define NE     8
#define TOPK   2
#define NROWS  (N_TOK * TOPK)   // 16384 routed rows total (top-2 of 8)

// ---------------- scratch (allocation-free rule: __device__ globals) --------
__device__ float g_h[(size_t)NROWS * D_HIDF];        // hidden activations (256 MB)
__device__ float g_partial[(size_t)NROWS * D_OUTF];  // per-row expert outputs (64 MB)
__device__ int   g_counts[NE];
__device__ int   g_offsets[NE + 1];
__device__ int   g_cursor[NE];
__device__ int   g_row_token[NROWS];   // routed row -> token id
__device__ int   g_token_row[NROWS];   // (token, slot) -> routed row
__device__ int   g_e_of[NROWS];        // (token, slot) -> expert
__device__ float g_w_of[NROWS];        // (token, slot) -> combine weight

// ---------------- kernel 0: reset routing counters --------------------------
__global__ void reset_kernel() {
    int t = threadIdx.x;
    if (t < NE) g_counts[t] = 0;
}

// ---------------- kernel 1: gating (1 warp / token) --------------------------
// scores = x @ Wg + bg ; softmax over 8 ; top-2 ; renormalized weights
__global__ __launch_bounds__(256) void gating_kernel(
    const float* __restrict__ x, const float* __restrict__ Wg,
    const float* __restrict__ bg)
{
    int gwarp = (blockIdx.x * blockDim.x + threadIdx.x) >> 5;
    int lane  = threadIdx.x & 31;
    if (gwarp >= N_TOK) return;
    const float* xr = x + (size_t)gwarp * D_INF;

    float acc[NE];
#pragma unroll
    for (int e = 0; e < NE; e++) acc[e] = 0.f;

    for (int k = lane; k < D_INF; k += 32) {
        float xv = xr[k];
        const float* wgr = Wg + (size_t)k * NE;
#pragma unroll
        for (int e = 0; e < NE; e++) acc[e] = fmaf(xv, wgr[e], acc[e]);
    }
#pragma unroll
    for (int off = 16; off; off >>= 1) {
#pragma unroll
        for (int e = 0; e < NE; e++)
            acc[e] += __shfl_xor_sync(0xffffffffu, acc[e], off);
    }

    if (lane == 0) {
        float s[NE];
#pragma unroll
        for (int e = 0; e < NE; e++) s[e] = acc[e] + bg[e];
        float mx = s[0];
#pragma unroll
        for (int e = 1; e < NE; e++) mx = fmaxf(mx, s[e]);
        float p[NE], sum = 0.f;
#pragma unroll
        for (int e = 0; e < NE; e++) { p[e] = expf(s[e] - mx); sum += p[e]; }
        float inv = 1.0f / sum;
#pragma unroll
        for (int e = 0; e < NE; e++) p[e] *= inv;

        int e0 = 0;
#pragma unroll
        for (int e = 1; e < NE; e++) if (s[e] > s[e0]) e0 = e;
        int e1 = (e0 == 0) ? 1 : 0;
#pragma unroll
        for (int e = 0; e < NE; e++) if (e != e0 && s[e] > s[e1]) e1 = e;

        float denom = p[e0] + p[e1] + 1e-8f;
        float w0 = p[e0] / denom, w1 = p[e1] / denom;

        int n = gwarp;
        g_e_of[2 * n + 0] = e0;  g_e_of[2 * n + 1] = e1;
        g_w_of[2 * n + 0] = w0;  g_w_of[2 * n + 1] = w1;
        atomicAdd(&g_counts[e0], 1);
        atomicAdd(&g_counts[e1], 1);
    }
}

// ---------------- kernel 2: exclusive scan over 8 experts --------------------
__global__ void scan_kernel() {
    int o = 0;
#pragma unroll
    for (int e = 0; e < NE; e++) {
        g_offsets[e] = o;
        g_cursor[e]  = o;
        o += g_counts[e];
    }
    g_offsets[NE] = o;
}

// ---------------- kernel 3: placement (token -> routed rows) ------------------
__global__ void place_kernel() {
    int n = blockIdx.x * blockDim.x + threadIdx.x;
    if (n >= N_TOK) return;
#pragma unroll
    for (int s = 0; s < TOPK; s++) {
        int e = g_e_of[2 * n + s];
        int r = atomicAdd(&g_cursor[e], 1);
        g_row_token[r] = n;
        g_token_row[2 * n + s] = r;
    }
}

// ---------------- grouped SGEMM 1: h = relu(gather(x) @ W1[e] + b1[e]) -------
// BM=BN=128, BK=16, 256 threads, 8x8 microtile, register prefetch.
__global__ __launch_bounds__(256, 2) void gemm1_kernel(
    const float* __restrict__ x, const float* __restrict__ W1,
    const float* __restrict__ b1)
{
    const int e    = blockIdx.z;
    const int rbeg = g_offsets[e];
    const int rend = g_offsets[e + 1];
    const int m0   = rbeg + blockIdx.y * 128;
    if (m0 >= rend) return;
    const int n0   = blockIdx.x * 128;

    __shared__ float As[16][128];
    __shared__ float Bs[16][128];
    __shared__ int   stok[128];

    const int tid = threadIdx.x;
    if (tid < 128) {
        int r = m0 + tid;
        stok[tid] = (r < rend) ? g_row_token[r] : -1;
    }
    __syncthreads();

    const int am = tid >> 1;            // 0..127
    const int ak = (tid & 1) << 3;      // 0 or 8
    const int bk = tid >> 4;            // 0..15
    const int bn = (tid & 15) << 3;     // 0..120
    const int ty = tid >> 4;            // 0..15
    const int tx = tid & 15;            // 0..15

    const int tok = stok[am];
    const float* aptr = (tok >= 0) ? (x + (size_t)tok * D_INF + ak) : nullptr;
    const float* bptr = W1 + ((size_t)e * D_INF + bk) * D_HIDF + n0 + bn;

    const int KT = D_INF / 16;  // 64

    float4 ra0, ra1, rb0, rb1;
    // preload tile 0
    if (aptr) {
        ra0 = *(const float4*)(aptr + 0);
        ra1 = *(const float4*)(aptr + 4);
    } else {
        ra0 = make_float4(0, 0, 0, 0); ra1 = ra0;
    }
    rb0 = *(const float4*)(bptr + 0);
    rb1 = *(const float4*)(bptr + 4);

    float acc[8][8];
#pragma unroll
    for (int i = 0; i < 8; i++)
#pragma unroll
        for (int j = 0; j < 8; j++) acc[i][j] = 0.f;

    for (int kt = 0; kt < KT; kt++) {
        // commit prefetched tile to smem
        As[ak + 0][am] = ra0.x; As[ak + 1][am] = ra0.y;
        As[ak + 2][am] = ra0.z; As[ak + 3][am] = ra0.w;
        As[ak + 4][am] = ra1.x; As[ak + 5][am] = ra1.y;
        As[ak + 6][am] = ra1.z; As[ak + 7][am] = ra1.w;
        *(float4*)&Bs[bk][bn]     = rb0;
        *(float4*)&Bs[bk][bn + 4] = rb1;
        __syncthreads();

        if (kt + 1 < KT) {
            int k0 = (kt + 1) * 16;
            if (aptr) {
                ra0 = *(const float4*)(aptr + k0 + 0);
                ra1 = *(const float4*)(aptr + k0 + 4);
            }
            rb0 = *(const float4*)(bptr + (size_t)k0 * D_HIDF + 0);
            rb1 = *(const float4*)(bptr + (size_t)k0 * D_HIDF + 4);
        }

#pragma unroll
        for (int p = 0; p < 16; p++) {
            float a[8], b[8];
            float4 t0 = *(const float4*)&As[p][ty * 8];
            float4 t1 = *(const float4*)&As[p][ty * 8 + 4];
            a[0]=t0.x; a[1]=t0.y; a[2]=t0.z; a[3]=t0.w;
            a[4]=t1.x; a[5]=t1.y; a[6]=t1.z; a[7]=t1.w;
            float4 u0 = *(const float4*)&Bs[p][tx * 8];
            float4 u1 = *(const float4*)&Bs[p][tx * 8 + 4];
            b[0]=u0.x; b[1]=u0.y; b[2]=u0.z; b[3]=u0.w;
            b[4]=u1.x; b[5]=u1.y; b[6]=u1.z; b[7]=u1.w;
#pragma unroll
            for (int i = 0; i < 8; i++)
#pragma unroll
                for (int j = 0; j < 8; j++)
                    acc[i][j] = fmaf(a[i], b[j], acc[i][j]);
        }
        __syncthreads();
    }

    // epilogue: + bias, relu, store to g_h
    const float* bias = b1 + (size_t)e * D_HIDF + n0 + tx * 8;
    float bj[8];
#pragma unroll
    for (int j = 0; j < 8; j++) bj[j] = bias[j];

#pragma unroll
    for (int i = 0; i < 8; i++) {
        int r = m0 + ty * 8 + i;
        if (r < rend) {
            float* hp = g_h + (size_t)r * D_HIDF + n0 + tx * 8;
            float v[8];
#pragma unroll
            for (int j = 0; j < 8; j++) v[j] = fmaxf(acc[i][j] + bj[j], 0.f);
            *(float4*)(hp + 0) = make_float4(v[0], v[1], v[2], v[3]);
            *(float4*)(hp + 4) = make_float4(v[4], v[5], v[6], v[7]);
        }
    }
}

// ---------------- grouped SGEMM 2: partial = h @ W2[e] + b2[e] ---------------
__global__ __launch_bounds__(256, 2) void gemm2_kernel(
    const float* __restrict__ W2, const float* __restrict__ b2)
{
    const int e    = blockIdx.z;
    const int rbeg = g_offsets[e];
    const int rend = g_offsets[e + 1];
    const int m0   = rbeg + blockIdx.y * 128;
    if (m0 >= rend) return;
    const int n0   = blockIdx.x * 128;

    __shared__ float As[16][128];
    __shared__ float Bs[16][128];

    const int tid = threadIdx.x;
    const int am = tid >> 1;
    const int ak = (tid & 1) << 3;
    const int bk = tid >> 4;
    const int bn = (tid & 15) << 3;
    const int ty = tid >> 4;
    const int tx = tid & 15;

    const int arow = m0 + am;
    const bool avalid = (arow < rend);
    const float* aptr = g_h + (size_t)arow * D_HIDF + ak;
    const float* bptr = W2 + ((size_t)e * D_HIDF + bk) * D_OUTF + n0 + bn;

    const int KT = D_HIDF / 16;  // 256

    float4 ra0, ra1, rb0, rb1;
    if (avalid) {
        ra0 = *(const float4*)(aptr + 0);
        ra1 = *(const float4*)(aptr + 4);
    } else {
        ra0 = make_float4(0, 0, 0, 0); ra1 = ra0;
    }
    rb0 = *(const float4*)(bptr + 0);
    rb1 = *(const float4*)(bptr + 4);

    float acc[8][8];
#pragma unroll
    for (int i = 0; i < 8; i++)
#pragma unroll
        for (int j = 0; j < 8; j++) acc[i][j] = 0.f;

    for (int kt = 0; kt < KT; kt++) {
        As[ak + 0][am] = ra0.x; As[ak + 1][am] = ra0.y;
        As[ak + 2][am] = ra0.z; As[ak + 3][am] = ra0.w;
        As[ak + 4][am] = ra1.x; As[ak + 5][am] = ra1.y;
        As[ak + 6][am] = ra1.z; As[ak + 7][am] = ra1.w;
        *(float4*)&Bs[bk][bn]     = rb0;
        *(float4*)&Bs[bk][bn + 4] = rb1;
        __syncthreads();

        if (kt + 1 < KT) {
            int k0 = (kt + 1) * 16;
            if (avalid) {
                ra0 = *(const float4*)(aptr + k0 + 0);
                ra1 = *(const float4*)(aptr + k0 + 4);
            }
            rb0 = *(const float4*)(bptr + (size_t)k0 * D_OUTF + 0);
            rb1 = *(const float4*)(bptr + (size_t)k0 * D_OUTF + 4);
        }

#pragma unroll
        for (int p = 0; p < 16; p++) {
            float a[8], b[8];
            float4 t0 = *(const float4*)&As[p][ty * 8];
            float4 t1 = *(const float4*)&As[p][ty * 8 + 4];
            a[0]=t0.x; a[1]=t0.y; a[2]=t0.z; a[3]=t0.w;
            a[4]=t1.x; a[5]=t1.y; a[6]=t1.z; a[7]=t1.w;
            float4 u0 = *(const float4*)&Bs[p][tx * 8];
            float4 u1 = *(const float4*)&Bs[p][tx * 8 + 4];
            b[0]=u0.x; b[1]=u0.y; b[2]=u0.z; b[3]=u0.w;
            b[4]=u1.x; b[5]=u1.y; b[6]=u1.z; b[7]=u1.w;
#pragma unroll
            for (int i = 0; i < 8; i++)
#pragma unroll
                for (int j = 0; j < 8; j++)
                    acc[i][j] = fmaf(a[i], b[j], acc[i][j]);
        }
        __syncthreads();
    }

    const float* bias = b2 + (size_t)e * D_OUTF + n0 + tx * 8;
    float bj[8];
#pragma unroll
    for (int j = 0; j < 8; j++) bj[j] = bias[j];

#pragma unroll
    for (int i = 0; i < 8; i++) {
        int r = m0 + ty * 8 + i;
        if (r < rend) {
            float* pp = g_partial + (size_t)r * D_OUTF + n0 + tx * 8;
            float v[8];
#pragma unroll
            for (int j = 0; j < 8; j++) v[j] = acc[i][j] + bj[j];
            *(float4*)(pp + 0) = make_float4(v[0], v[1], v[2], v[3]);
            *(float4*)(pp + 4) = make_float4(v[4], v[5], v[6], v[7]);
        }
    }
}

// ---------------- kernel 6: weighted combine --------------------------------
__global__ __launch_bounds__(256) void combine_kernel(float* __restrict__ out) {
    int idx = blockIdx.x * blockDim.x + threadIdx.x;  // over N_TOK * D_OUT/4
    int n = idx >> 8;                                 // 256 float4 per token
    int c = (idx & 255) << 2;
    if (n >= N_TOK) return;
    float w0 = g_w_of[2 * n + 0], w1 = g_w_of[2 * n + 1];
    int   r0 = g_token_row[2 * n + 0], r1 = g_token_row[2 * n + 1];
    float4 p0 = *(const float4*)(g_partial + (size_t)r0 * D_OUTF + c);
    float4 p1 = *(const float4*)(g_partial + (size_t)r1 * D_OUTF + c);
    float4 o;
    o.x = w0 * p0.x + w1 * p1.x;
    o.y = w0 * p0.y + w1 * p1.y;
    o.z = w0 * p0.z + w1 * p1.z;
    o.w = w0 * p0.w + w1 * p1.w;
    *(float4*)(out + (size_t)n * D_OUTF + c) = o;
}

// ---------------- launcher ----------------------------------------------------
extern "C" void kernel_launch(void* const* d_in, const int* in_sizes, int n_in,
                              void* d_out, int out_size) {
    const float* x  = (const float*)d_in[0];
    const float* W1 = (const float*)d_in[1];
    const float* b1 = (const float*)d_in[2];
    const float* W2 = (const float*)d_in[3];
    const float* b2 = (const float*)d_in[4];
    const float* Wg = (const float*)d_in[5];
    const float* bg = (const float*)d_in[6];
    // d_in[7] = k (fixed at 2 for this problem)
    float* out = (float*)d_out;

    reset_kernel<<<1, 32>>>();
    gating_kernel<<<N_TOK / 8, 256>>>(x, Wg, bg);
    scan_kernel<<<1, 1>>>();
    place_kernel<<<N_TOK / 256, 256>>>();
    gemm1_kernel<<<dim3(D_HIDF / 128, 64, NE), 256>>>(x, W1, b1);
    gemm2_kernel<<<dim3(D_OUTF / 128, 64, NE), 256>>>(W2, b2);
    combine_kernel<<<(N_TOK * D_OUTF / 4) / 256, 256>>>(out);
}

// round 6
// speedup vs baseline: 1.6419x; 1.6419x over previous
#include <cuda_runtime.h>
#include <cuda_bf16.h>
#include <math.h>
#include <stdint.h>

// Problem constants
#define N_TOK  8192
#define D_INF  1024
#define D_HIDF 4096
#define D_OUTF 1024
#define NE     8
#define TOPK   2
#define NROWS  (N_TOK * TOPK)

// ---------------- scratch (__device__ globals; allocation-free rule) --------
__device__ __align__(256) __nv_bfloat16 g_xhi[(size_t)N_TOK * D_INF];
__device__ __align__(256) __nv_bfloat16 g_xlo[(size_t)N_TOK * D_INF];
__device__ __align__(256) __nv_bfloat16 g_w1thi[(size_t)NE * D_HIDF * D_INF];  // [E][Nhid][Kin]
__device__ __align__(256) __nv_bfloat16 g_w1tlo[(size_t)NE * D_HIDF * D_INF];
__device__ __align__(256) __nv_bfloat16 g_w2thi[(size_t)NE * D_OUTF * D_HIDF]; // [E][Nout][Khid]
__device__ __align__(256) __nv_bfloat16 g_w2tlo[(size_t)NE * D_OUTF * D_HIDF];
__device__ __align__(256) __nv_bfloat16 g_hhi[(size_t)NROWS * D_HIDF];
__device__ __align__(256) __nv_bfloat16 g_hlo[(size_t)NROWS * D_HIDF];
__device__ __align__(256) float g_partial[(size_t)NROWS * D_OUTF];
__device__ int   g_counts[NE];
__device__ int   g_offsets[NE + 1];
__device__ int   g_cursor[NE];
__device__ int   g_row_token[NROWS];
__device__ int   g_token_row[NROWS];
__device__ int   g_e_of[NROWS];
__device__ float g_w_of[NROWS];

// ---------------- PTX helpers (base sm_103 only; NO 'a' features) -----------
__device__ __forceinline__ uint32_t smem_u32(const void* p) {
    uint32_t a;
    asm("{ .reg .u64 t; cvta.to.shared.u64 t, %1; cvt.u32.u64 %0, t; }"
        : "=r"(a) : "l"(p));
    return a;
}
__device__ __forceinline__ void cp16(uint32_t dst, const void* src) {
    unsigned long long g = (unsigned long long)__cvta_generic_to_global(src);
    asm volatile("cp.async.cg.shared.global [%0], [%1], 16;" :: "r"(dst), "l"(g));
}
#define CP_COMMIT() asm volatile("cp.async.commit_group;" ::: "memory")
template <int Np> __device__ __forceinline__ void cp_wait() {
    asm volatile("cp.async.wait_group %0;" :: "n"(Np) : "memory");
}
__device__ __forceinline__ void ldsm_x4(uint32_t& r0, uint32_t& r1, uint32_t& r2,
                                        uint32_t& r3, uint32_t addr) {
    asm volatile("ldmatrix.sync.aligned.m8n8.x4.shared.b16 {%0,%1,%2,%3}, [%4];"
                 : "=r"(r0), "=r"(r1), "=r"(r2), "=r"(r3) : "r"(addr));
}
__device__ __forceinline__ void mma_bf16(float* c, const uint32_t* a, uint32_t b0,
                                         uint32_t b1) {
    asm volatile(
        "mma.sync.aligned.m16n8k16.row.col.f32.bf16.bf16.f32 "
        "{%0,%1,%2,%3}, {%4,%5,%6,%7}, {%8,%9}, {%0,%1,%2,%3};"
        : "+f"(c[0]), "+f"(c[1]), "+f"(c[2]), "+f"(c[3])
        : "r"(a[0]), "r"(a[1]), "r"(a[2]), "r"(a[3]), "r"(b0), "r"(b1));
}
__device__ __forceinline__ uint32_t bpack(__nv_bfloat16 a, __nv_bfloat16 b) {
    return (uint32_t)__bfloat16_as_ushort(a) | ((uint32_t)__bfloat16_as_ushort(b) << 16);
}

// ---------------- kernel 0: reset --------------------------------------------
__global__ void reset_kernel() {
    int t = threadIdx.x;
    if (t < NE) g_counts[t] = 0;
}

// ---------------- kernel 1: gating -------------------------------------------
__global__ __launch_bounds__(256) void gating_kernel(
    const float* __restrict__ x, const float* __restrict__ Wg,
    const float* __restrict__ bg)
{
    int gwarp = (blockIdx.x * blockDim.x + threadIdx.x) >> 5;
    int lane  = threadIdx.x & 31;
    if (gwarp >= N_TOK) return;
    const float* xr = x + (size_t)gwarp * D_INF;

    float acc[NE];
#pragma unroll
    for (int e = 0; e < NE; e++) acc[e] = 0.f;
    for (int k = lane; k < D_INF; k += 32) {
        float xv = xr[k];
        const float* wgr = Wg + (size_t)k * NE;
#pragma unroll
        for (int e = 0; e < NE; e++) acc[e] = fmaf(xv, wgr[e], acc[e]);
    }
#pragma unroll
    for (int off = 16; off; off >>= 1)
#pragma unroll
        for (int e = 0; e < NE; e++)
            acc[e] += __shfl_xor_sync(0xffffffffu, acc[e], off);

    if (lane == 0) {
        float s[NE];
#pragma unroll
        for (int e = 0; e < NE; e++) s[e] = acc[e] + bg[e];
        float mx = s[0];
#pragma unroll
        for (int e = 1; e < NE; e++) mx = fmaxf(mx, s[e]);
        float p[NE], sum = 0.f;
#pragma unroll
        for (int e = 0; e < NE; e++) { p[e] = expf(s[e] - mx); sum += p[e]; }
        float inv = 1.0f / sum;
#pragma unroll
        for (int e = 0; e < NE; e++) p[e] *= inv;
        int e0 = 0;
#pragma unroll
        for (int e = 1; e < NE; e++) if (s[e] > s[e0]) e0 = e;
        int e1 = (e0 == 0) ? 1 : 0;
#pragma unroll
        for (int e = 0; e < NE; e++) if (e != e0 && s[e] > s[e1]) e1 = e;
        float denom = p[e0] + p[e1] + 1e-8f;
        int n = gwarp;
        g_e_of[2*n+0] = e0;  g_e_of[2*n+1] = e1;
        g_w_of[2*n+0] = p[e0] / denom;  g_w_of[2*n+1] = p[e1] / denom;
        atomicAdd(&g_counts[e0], 1);
        atomicAdd(&g_counts[e1], 1);
    }
}

// ---------------- kernel 2/3: scan + placement -------------------------------
__global__ void scan_kernel() {
    int o = 0;
#pragma unroll
    for (int e = 0; e < NE; e++) { g_offsets[e] = o; g_cursor[e] = o; o += g_counts[e]; }
    g_offsets[NE] = o;
}
__global__ void place_kernel() {
    int n = blockIdx.x * blockDim.x + threadIdx.x;
    if (n >= N_TOK) return;
#pragma unroll
    for (int s = 0; s < TOPK; s++) {
        int e = g_e_of[2*n+s];
        int r = atomicAdd(&g_cursor[e], 1);
        g_row_token[r] = n;
        g_token_row[2*n+s] = r;
    }
}

// ---------------- prepass: x -> bf16 hi/lo -----------------------------------
__global__ __launch_bounds__(256) void cvtx_kernel(const float* __restrict__ x) {
    size_t i = ((size_t)blockIdx.x * 256 + threadIdx.x) * 4;
    float4 v = *(const float4*)(x + i);
    __nv_bfloat16 h0 = __float2bfloat16(v.x), h1 = __float2bfloat16(v.y);
    __nv_bfloat16 h2 = __float2bfloat16(v.z), h3 = __float2bfloat16(v.w);
    __nv_bfloat16 l0 = __float2bfloat16(v.x - __bfloat162float(h0));
    __nv_bfloat16 l1 = __float2bfloat16(v.y - __bfloat162float(h1));
    __nv_bfloat16 l2 = __float2bfloat16(v.z - __bfloat162float(h2));
    __nv_bfloat16 l3 = __float2bfloat16(v.w - __bfloat162float(h3));
    uint2 hh, ll;
    hh.x = bpack(h0, h1); hh.y = bpack(h2, h3);
    ll.x = bpack(l0, l1); ll.y = bpack(l2, l3);
    *(uint2*)(g_xhi + i) = hh;
    *(uint2*)(g_xlo + i) = ll;
}

// ---------------- prepass: W [E][K][N] -> WT hi/lo [E][N][K] ------------------
template <int K, int N, int WCH>
__global__ void tpose_kernel(const float* __restrict__ Wsrc) {
    __shared__ float t[32][33];
    int e  = blockIdx.z;
    int n0 = blockIdx.x * 32, k0 = blockIdx.y * 32;
    int tx = threadIdx.x, ty = threadIdx.y;  // 32 x 8
    const float* src = Wsrc + ((size_t)e * K + k0) * N + n0;
#pragma unroll
    for (int i = 0; i < 4; i++)
        t[ty + 8*i][tx] = src[(size_t)(ty + 8*i) * N + tx];
    __syncthreads();
    __nv_bfloat16* Thi = (WCH == 1) ? g_w1thi : g_w2thi;
    __nv_bfloat16* Tlo = (WCH == 1) ? g_w1tlo : g_w2tlo;
    size_t ob = ((size_t)e * N + n0) * K + k0;
#pragma unroll
    for (int i = 0; i < 4; i++) {
        float v = t[tx][ty + 8*i];
        __nv_bfloat16 h = __float2bfloat16(v);
        Thi[ob + (size_t)(ty + 8*i) * K + tx] = h;
        Tlo[ob + (size_t)(ty + 8*i) * K + tx] = __float2bfloat16(v - __bfloat162float(h));
    }
}

// ---------------- grouped HMMA GEMM (bf16 hi/lo 3-pass) -----------------------
// BM=128, BN=128, BK=32, 256 threads (8 warps, warp tile 64x32), 3-stage cp.async.
// smem per stage: A (hi rows 0-127, lo rows 128-255) then B (hi/lo), 80B row pitch.
#define ROWP      80
#define B_REGION  (256 * ROWP)          // 20480
#define STAGE_SZ  (2 * B_REGION)        // 40960
#define NSTAGE    3
#define SMEM_DYN  (NSTAGE * STAGE_SZ + 256)

template <int G>
__global__ __launch_bounds__(256, 1) void gemm_kernel(const float* __restrict__ bias_g) {
    constexpr int KD = (G == 1) ? D_INF : D_HIDF;
    constexpr int NT = (G == 1) ? D_HIDF : D_OUTF;
    constexpr int KT = KD / 32;

    const int e    = blockIdx.z;
    const int rbeg = g_offsets[e];
    const int rend = g_offsets[e + 1];
    const int m0   = rbeg + blockIdx.y * 128;
    if (m0 >= rend) return;
    const int n0   = blockIdx.x * 128;

    __shared__ float sbias[128];
    extern __shared__ char dsm[];
    const uint32_t dynb = (smem_u32(dsm) + 127u) & ~127u;

    const int tid  = threadIdx.x;
    const int wid  = tid >> 5;
    const int lane = tid & 31;

    if (tid < 128) sbias[tid] = bias_g[(size_t)e * NT + n0 + tid];

    const __nv_bfloat16* ahi_g = (G == 1) ? g_xhi : g_hhi;
    const __nv_bfloat16* alo_g = (G == 1) ? g_xlo : g_hlo;
    const __nv_bfloat16* bhi_g = (G == 1) ? g_w1thi : g_w2thi;
    const __nv_bfloat16* blo_g = (G == 1) ? g_w1tlo : g_w2tlo;

    // ---- loader geometry: 4 halves x 64 threads; 2 rows x 4 chunks each ----
    const int half = tid >> 6;          // 0:Ahi 1:Alo 2:Bhi 3:Blo
    const int u    = tid & 63;
    const __nv_bfloat16* gsrc[2];
    uint32_t dstoff[2];
#pragma unroll
    for (int rr = 0; rr < 2; rr++) {
        int r = 2 * u + rr;             // 0..127 within half
        if (half < 2) {
            int gr = m0 + r;
            if (gr >= rend) gr = rbeg;  // valid garbage row; epilogue masks
            size_t rowb = (G == 1) ? (size_t)g_row_token[gr] * KD : (size_t)gr * KD;
            gsrc[rr]   = ((half == 0) ? ahi_g : alo_g) + rowb;
            dstoff[rr] = (uint32_t)((half * 128 + r) * ROWP);
        } else {
            size_t rowb = ((size_t)e * NT + n0 + r) * KD;
            gsrc[rr]   = ((half == 2) ? bhi_g : blo_g) + rowb;
            dstoff[rr] = (uint32_t)(B_REGION + ((half - 2) * 128 + r) * ROWP);
        }
    }

    auto load_stage = [&](int kt, int stg) {
        const uint32_t sb = dynb + (uint32_t)stg * STAGE_SZ;
        const int k0 = kt * 32;
#pragma unroll
        for (int rr = 0; rr < 2; rr++) {
            const __nv_bfloat16* src = gsrc[rr] + k0;
            const uint32_t dst = sb + dstoff[rr];
#pragma unroll
            for (int c = 0; c < 4; c++) cp16(dst + c * 16, src + c * 8);
        }
        CP_COMMIT();
    };

    // ---- fragment address bases (per-thread invariants) ----
    const int wm = (wid >> 2) * 64;     // warp M offset: 0 or 64
    const int wn = (wid & 3) * 32;      // warp N offset: 0,32,64,96
    const int mtx = lane >> 3;          // ldmatrix matrix id 0..3
    const int inr = lane & 7;
    // A x4 tile: matrices {m0-7 k0, m8-15 k0, m0-7 k8, m8-15 k8}
    const uint32_t aoff = (uint32_t)((wm + (mtx & 1) * 8 + inr) * ROWP + (mtx >> 1) * 16);
    // B x4 pair: matrices {n0-7 k0, n0-7 k8, n8-15 k0, n8-15 k8}
    const uint32_t boff = (uint32_t)(B_REGION + (wn + (mtx >> 1) * 8 + inr) * ROWP + (mtx & 1) * 16);

    float acc[4][4][4];
#pragma unroll
    for (int i = 0; i < 4; i++)
#pragma unroll
        for (int j = 0; j < 4; j++)
#pragma unroll
            for (int q = 0; q < 4; q++) acc[i][j][q] = 0.f;

    load_stage(0, 0);
    load_stage(1, 1);

    for (int kt = 0; kt < KT; kt++) {
        cp_wait<1>();
        __syncthreads();
        if (kt + 2 < KT) load_stage(kt + 2, (kt + 2) % NSTAGE);

        const uint32_t sb = dynb + (uint32_t)(kt % NSTAGE) * STAGE_SZ;
#pragma unroll
        for (int ks = 0; ks < 2; ks++) {
            uint32_t ah[4][4], al[4][4], bh[2][4], bl[2][4];
#pragma unroll
            for (int mt = 0; mt < 4; mt++) {
                uint32_t a = sb + aoff + (uint32_t)(mt * 16 * ROWP + ks * 32);
                ldsm_x4(ah[mt][0], ah[mt][1], ah[mt][2], ah[mt][3], a);
                ldsm_x4(al[mt][0], al[mt][1], al[mt][2], al[mt][3], a + 128 * ROWP);
            }
#pragma unroll
            for (int np = 0; np < 2; np++) {
                uint32_t b = sb + boff + (uint32_t)(np * 16 * ROWP + ks * 32);
                ldsm_x4(bh[np][0], bh[np][1], bh[np][2], bh[np][3], b);
                ldsm_x4(bl[np][0], bl[np][1], bl[np][2], bl[np][3], b + 128 * ROWP);
            }
#pragma unroll
            for (int mt = 0; mt < 4; mt++)
#pragma unroll
                for (int nt = 0; nt < 4; nt++) {
                    const int np = nt >> 1, h2 = (nt & 1) * 2;
                    mma_bf16(acc[mt][nt], ah[mt], bh[np][h2], bh[np][h2 + 1]);
                    mma_bf16(acc[mt][nt], ah[mt], bl[np][h2], bl[np][h2 + 1]);
                    mma_bf16(acc[mt][nt], al[mt], bh[np][h2], bh[np][h2 + 1]);
                }
        }
        __syncthreads();
    }
    cp_wait<0>();

    // ---- epilogue ----
    const int erow = m0 + wm + (lane >> 2);
    const int ecol = n0 + wn + 2 * (lane & 3);
#pragma unroll
    for (int mt = 0; mt < 4; mt++) {
#pragma unroll
        for (int nt = 0; nt < 4; nt++) {
            const int col = ecol + nt * 8;
            const float bs0 = sbias[col - n0], bs1 = sbias[col - n0 + 1];
#pragma unroll
            for (int hrow = 0; hrow < 2; hrow++) {
                const int row = erow + mt * 16 + hrow * 8;
                if (row < rend) {
                    float v0 = acc[mt][nt][2 * hrow + 0] + bs0;
                    float v1 = acc[mt][nt][2 * hrow + 1] + bs1;
                    size_t off = (size_t)row * NT + col;
                    if (G == 1) {
                        v0 = fmaxf(v0, 0.f);
                        v1 = fmaxf(v1, 0.f);
                        __nv_bfloat16 h0 = __float2bfloat16(v0);
                        __nv_bfloat16 h1 = __float2bfloat16(v1);
                        __nv_bfloat16 l0 = __float2bfloat16(v0 - __bfloat162float(h0));
                        __nv_bfloat16 l1 = __float2bfloat16(v1 - __bfloat162float(h1));
                        *(uint32_t*)(g_hhi + off) = bpack(h0, h1);
                        *(uint32_t*)(g_hlo + off) = bpack(l0, l1);
                    } else {
                        float2 o; o.x = v0; o.y = v1;
                        *(float2*)(g_partial + off) = o;
                    }
                }
            }
        }
    }
}

// ---------------- combine -----------------------------------------------------
__global__ __launch_bounds__(256) void combine_kernel(float* __restrict__ out) {
    int idx = blockIdx.x * blockDim.x + threadIdx.x;
    int n = idx >> 8;
    int cc = (idx & 255) << 2;
    if (n >= N_TOK) return;
    float w0 = g_w_of[2*n+0], w1 = g_w_of[2*n+1];
    int   r0 = g_token_row[2*n+0], r1 = g_token_row[2*n+1];
    float4 p0 = *(const float4*)(g_partial + (size_t)r0 * D_OUTF + cc);
    float4 p1 = *(const float4*)(g_partial + (size_t)r1 * D_OUTF + cc);
    float4 o;
    o.x = w0*p0.x + w1*p1.x;  o.y = w0*p0.y + w1*p1.y;
    o.z = w0*p0.z + w1*p1.z;  o.w = w0*p0.w + w1*p1.w;
    *(float4*)(out + (size_t)n * D_OUTF + cc) = o;
}

// ---------------- launcher ----------------------------------------------------
extern "C" void kernel_launch(void* const* d_in, const int* in_sizes, int n_in,
                              void* d_out, int out_size) {
    const float* x  = (const float*)d_in[0];
    const float* W1 = (const float*)d_in[1];
    const float* b1 = (const float*)d_in[2];
    const float* W2 = (const float*)d_in[3];
    const float* b2 = (const float*)d_in[4];
    const float* Wg = (const float*)d_in[5];
    const float* bg = (const float*)d_in[6];
    float* out = (float*)d_out;

    cudaFuncSetAttribute(gemm_kernel<1>, cudaFuncAttributeMaxDynamicSharedMemorySize, SMEM_DYN);
    cudaFuncSetAttribute(gemm_kernel<2>, cudaFuncAttributeMaxDynamicSharedMemorySize, SMEM_DYN);

    reset_kernel<<<1, 32>>>();
    gating_kernel<<<N_TOK / 8, 256>>>(x, Wg, bg);
    scan_kernel<<<1, 1>>>();
    place_kernel<<<N_TOK / 256, 256>>>();

    cvtx_kernel<<<(N_TOK * D_INF / 4) / 256, 256>>>(x);
    tpose_kernel<D_INF,  D_HIDF, 1><<<dim3(D_HIDF/32, D_INF/32,  NE), dim3(32, 8)>>>(W1);
    tpose_kernel<D_HIDF, D_OUTF, 2><<<dim3(D_OUTF/32, D_HIDF/32, NE), dim3(32, 8)>>>(W2);

    gemm_kernel<1><<<dim3(D_HIDF/128, 64, NE), 256, SMEM_DYN>>>(b1);
    gemm_kernel<2><<<dim3(D_OUTF/128, 64, NE), 256, SMEM_DYN>>>(b2);

    combine_kernel<<<(N_TOK * D_OUTF / 4) / 256, 256>>>(out);
}

// round 7
// speedup vs baseline: 1.6550x; 1.0080x over previous
#include <cuda_runtime.h>
#include <cuda_bf16.h>
#include <math.h>
#include <stdint.h>

// Problem constants
#define N_TOK  8192
#define D_INF  1024
#define D_HIDF 4096
#define D_OUTF 1024
#define NE     8
#define TOPK   2
#define NROWS  (N_TOK * TOPK)

// ---------------- scratch (__device__ globals; allocation-free rule) --------
__device__ __align__(256) __nv_bfloat16 g_xhi[(size_t)N_TOK * D_INF];
__device__ __align__(256) __nv_bfloat16 g_xlo[(size_t)N_TOK * D_INF];
__device__ __align__(256) __nv_bfloat16 g_w1thi[(size_t)NE * D_HIDF * D_INF];  // [E][Nhid][Kin]
__device__ __align__(256) __nv_bfloat16 g_w1tlo[(size_t)NE * D_HIDF * D_INF];
__device__ __align__(256) __nv_bfloat16 g_w2thi[(size_t)NE * D_OUTF * D_HIDF]; // [E][Nout][Khid]
__device__ __align__(256) __nv_bfloat16 g_w2tlo[(size_t)NE * D_OUTF * D_HIDF];
__device__ __align__(256) __nv_bfloat16 g_hhi[(size_t)NROWS * D_HIDF];
__device__ __align__(256) __nv_bfloat16 g_hlo[(size_t)NROWS * D_HIDF];
__device__ __align__(256) float g_partial[(size_t)NROWS * D_OUTF];
__device__ int   g_counts[NE];
__device__ int   g_offsets[NE + 1];
__device__ int   g_cursor[NE];
__device__ int   g_row_token[NROWS];
__device__ int   g_token_row[NROWS];
__device__ int   g_e_of[NROWS];
__device__ float g_w_of[NROWS];

// ---------------- PTX helpers (base sm_103 only; NO 'a' features) -----------
__device__ __forceinline__ uint32_t smem_u32(const void* p) {
    uint32_t a;
    asm("{ .reg .u64 t; cvta.to.shared.u64 t, %1; cvt.u32.u64 %0, t; }"
        : "=r"(a) : "l"(p));
    return a;
}
__device__ __forceinline__ void cp16(uint32_t dst, const void* src) {
    unsigned long long g = (unsigned long long)__cvta_generic_to_global(src);
    asm volatile("cp.async.cg.shared.global [%0], [%1], 16;" :: "r"(dst), "l"(g));
}
#define CP_COMMIT() asm volatile("cp.async.commit_group;" ::: "memory")
template <int Np> __device__ __forceinline__ void cp_wait() {
    asm volatile("cp.async.wait_group %0;" :: "n"(Np) : "memory");
}
__device__ __forceinline__ void ldsm_x4(uint32_t& r0, uint32_t& r1, uint32_t& r2,
                                        uint32_t& r3, uint32_t addr) {
    asm volatile("ldmatrix.sync.aligned.m8n8.x4.shared.b16 {%0,%1,%2,%3}, [%4];"
                 : "=r"(r0), "=r"(r1), "=r"(r2), "=r"(r3) : "r"(addr));
}
__device__ __forceinline__ void mma_bf16(float* c, const uint32_t* a, uint32_t b0,
                                         uint32_t b1) {
    asm volatile(
        "mma.sync.aligned.m16n8k16.row.col.f32.bf16.bf16.f32 "
        "{%0,%1,%2,%3}, {%4,%5,%6,%7}, {%8,%9}, {%0,%1,%2,%3};"
        : "+f"(c[0]), "+f"(c[1]), "+f"(c[2]), "+f"(c[3])
        : "r"(a[0]), "r"(a[1]), "r"(a[2]), "r"(a[3]), "r"(b0), "r"(b1));
}
__device__ __forceinline__ uint32_t bpack(__nv_bfloat16 a, __nv_bfloat16 b) {
    return (uint32_t)__bfloat16_as_ushort(a) | ((uint32_t)__bfloat16_as_ushort(b) << 16);
}

// ---------------- kernel 0: reset --------------------------------------------
__global__ void reset_kernel() {
    int t = threadIdx.x;
    if (t < NE) g_counts[t] = 0;
}

// ---------------- kernel 1: gating -------------------------------------------
__global__ __launch_bounds__(256) void gating_kernel(
    const float* __restrict__ x, const float* __restrict__ Wg,
    const float* __restrict__ bg)
{
    int gwarp = (blockIdx.x * blockDim.x + threadIdx.x) >> 5;
    int lane  = threadIdx.x & 31;
    if (gwarp >= N_TOK) return;
    const float* xr = x + (size_t)gwarp * D_INF;

    float acc[NE];
#pragma unroll
    for (int e = 0; e < NE; e++) acc[e] = 0.f;
    for (int k = lane; k < D_INF; k += 32) {
        float xv = xr[k];
        const float* wgr = Wg + (size_t)k * NE;
#pragma unroll
        for (int e = 0; e < NE; e++) acc[e] = fmaf(xv, wgr[e], acc[e]);
    }
#pragma unroll
    for (int off = 16; off; off >>= 1)
#pragma unroll
        for (int e = 0; e < NE; e++)
            acc[e] += __shfl_xor_sync(0xffffffffu, acc[e], off);

    if (lane == 0) {
        float s[NE];
#pragma unroll
        for (int e = 0; e < NE; e++) s[e] = acc[e] + bg[e];
        float mx = s[0];
#pragma unroll
        for (int e = 1; e < NE; e++) mx = fmaxf(mx, s[e]);
        float p[NE], sum = 0.f;
#pragma unroll
        for (int e = 0; e < NE; e++) { p[e] = expf(s[e] - mx); sum += p[e]; }
        float inv = 1.0f / sum;
#pragma unroll
        for (int e = 0; e < NE; e++) p[e] *= inv;
        int e0 = 0;
#pragma unroll
        for (int e = 1; e < NE; e++) if (s[e] > s[e0]) e0 = e;
        int e1 = (e0 == 0) ? 1 : 0;
#pragma unroll
        for (int e = 0; e < NE; e++) if (e != e0 && s[e] > s[e1]) e1 = e;
        float denom = p[e0] + p[e1] + 1e-8f;
        int n = gwarp;
        g_e_of[2*n+0] = e0;  g_e_of[2*n+1] = e1;
        g_w_of[2*n+0] = p[e0] / denom;  g_w_of[2*n+1] = p[e1] / denom;
        atomicAdd(&g_counts[e0], 1);
        atomicAdd(&g_counts[e1], 1);
    }
}

// ---------------- kernel 2/3: scan + placement -------------------------------
__global__ void scan_kernel() {
    int o = 0;
#pragma unroll
    for (int e = 0; e < NE; e++) { g_offsets[e] = o; g_cursor[e] = o; o += g_counts[e]; }
    g_offsets[NE] = o;
}
__global__ void place_kernel() {
    int n = blockIdx.x * blockDim.x + threadIdx.x;
    if (n >= N_TOK) return;
#pragma unroll
    for (int s = 0; s < TOPK; s++) {
        int e = g_e_of[2*n+s];
        int r = atomicAdd(&g_cursor[e], 1);
        g_row_token[r] = n;
        g_token_row[2*n+s] = r;
    }
}

// ---------------- prepass: x -> bf16 hi/lo -----------------------------------
__global__ __launch_bounds__(256) void cvtx_kernel(const float* __restrict__ x) {
    size_t i = ((size_t)blockIdx.x * 256 + threadIdx.x) * 4;
    float4 v = *(const float4*)(x + i);
    __nv_bfloat16 h0 = __float2bfloat16(v.x), h1 = __float2bfloat16(v.y);
    __nv_bfloat16 h2 = __float2bfloat16(v.z), h3 = __float2bfloat16(v.w);
    __nv_bfloat16 l0 = __float2bfloat16(v.x - __bfloat162float(h0));
    __nv_bfloat16 l1 = __float2bfloat16(v.y - __bfloat162float(h1));
    __nv_bfloat16 l2 = __float2bfloat16(v.z - __bfloat162float(h2));
    __nv_bfloat16 l3 = __float2bfloat16(v.w - __bfloat162float(h3));
    uint2 hh, ll;
    hh.x = bpack(h0, h1); hh.y = bpack(h2, h3);
    ll.x = bpack(l0, l1); ll.y = bpack(l2, l3);
    *(uint2*)(g_xhi + i) = hh;
    *(uint2*)(g_xlo + i) = ll;
}

// ---------------- prepass: W [E][K][N] -> WT hi/lo [E][N][K] ------------------
template <int K, int N, int WCH>
__global__ void tpose_kernel(const float* __restrict__ Wsrc) {
    __shared__ float t[32][33];
    int e  = blockIdx.z;
    int n0 = blockIdx.x * 32, k0 = blockIdx.y * 32;
    int tx = threadIdx.x, ty = threadIdx.y;  // 32 x 8
    const float* src = Wsrc + ((size_t)e * K + k0) * N + n0;
#pragma unroll
    for (int i = 0; i < 4; i++)
        t[ty + 8*i][tx] = src[(size_t)(ty + 8*i) * N + tx];
    __syncthreads();
    __nv_bfloat16* Thi = (WCH == 1) ? g_w1thi : g_w2thi;
    __nv_bfloat16* Tlo = (WCH == 1) ? g_w1tlo : g_w2tlo;
    size_t ob = ((size_t)e * N + n0) * K + k0;
#pragma unroll
    for (int i = 0; i < 4; i++) {
        float v = t[tx][ty + 8*i];
        __nv_bfloat16 h = __float2bfloat16(v);
        Thi[ob + (size_t)(ty + 8*i) * K + tx] = h;
        Tlo[ob + (size_t)(ty + 8*i) * K + tx] = __float2bfloat16(v - __bfloat162float(h));
    }
}

// ---------------- grouped HMMA GEMM (bf16 hi/lo 3-pass) -----------------------
// BM=128, BN=128, BK=64, 256 threads (8 warps, warp tile 64x32), 3-stage cp.async.
// smem per stage: A (hi rows 0-127, lo rows 128-255) then B (hi/lo), 144B row pitch.
#define ROWP      144
#define B_REGION  (256 * ROWP)          // 36864
#define STAGE_SZ  (2 * B_REGION)        // 73728
#define NSTAGE    3
#define SMEM_DYN  (NSTAGE * STAGE_SZ + 256)

template <int G>
__global__ __launch_bounds__(256, 1) void gemm_kernel(const float* __restrict__ bias_g) {
    constexpr int KD = (G == 1) ? D_INF : D_HIDF;
    constexpr int NT = (G == 1) ? D_HIDF : D_OUTF;
    constexpr int KT = KD / 64;

    const int e    = blockIdx.z;
    const int rbeg = g_offsets[e];
    const int rend = g_offsets[e + 1];
    const int m0   = rbeg + blockIdx.y * 128;
    if (m0 >= rend) return;
    const int n0   = blockIdx.x * 128;

    __shared__ float sbias[128];
    extern __shared__ char dsm[];
    const uint32_t dynb = (smem_u32(dsm) + 127u) & ~127u;

    const int tid  = threadIdx.x;
    const int wid  = tid >> 5;
    const int lane = tid & 31;

    if (tid < 128) sbias[tid] = bias_g[(size_t)e * NT + n0 + tid];

    const __nv_bfloat16* ahi_g = (G == 1) ? g_xhi : g_hhi;
    const __nv_bfloat16* alo_g = (G == 1) ? g_xlo : g_hlo;
    const __nv_bfloat16* bhi_g = (G == 1) ? g_w1thi : g_w2thi;
    const __nv_bfloat16* blo_g = (G == 1) ? g_w1tlo : g_w2tlo;

    // ---- loader geometry: 4 halves x 64 threads; 2 rows x 8 chunks each ----
    const int half = tid >> 6;          // 0:Ahi 1:Alo 2:Bhi 3:Blo
    const int u    = tid & 63;
    const __nv_bfloat16* gsrc[2];
    uint32_t dstoff[2];
#pragma unroll
    for (int rr = 0; rr < 2; rr++) {
        int r = 2 * u + rr;             // 0..127 within half
        if (half < 2) {
            int gr = m0 + r;
            if (gr >= rend) gr = rbeg;  // valid garbage row; epilogue masks
            size_t rowb = (G == 1) ? (size_t)g_row_token[gr] * KD : (size_t)gr * KD;
            gsrc[rr]   = ((half == 0) ? ahi_g : alo_g) + rowb;
            dstoff[rr] = (uint32_t)((half * 128 + r) * ROWP);
        } else {
            size_t rowb = ((size_t)e * NT + n0 + r) * KD;
            gsrc[rr]   = ((half == 2) ? bhi_g : blo_g) + rowb;
            dstoff[rr] = (uint32_t)(B_REGION + ((half - 2) * 128 + r) * ROWP);
        }
    }

    auto load_stage = [&](int kt, int stg) {
        const uint32_t sb = dynb + (uint32_t)stg * STAGE_SZ;
        const int k0 = kt * 64;
#pragma unroll
        for (int rr = 0; rr < 2; rr++) {
            const __nv_bfloat16* src = gsrc[rr] + k0;
            const uint32_t dst = sb + dstoff[rr];
#pragma unroll
            for (int c = 0; c < 8; c++) cp16(dst + c * 16, src + c * 8);
        }
        CP_COMMIT();
    };

    // ---- fragment address bases (per-thread invariants) ----
    const int wm = (wid >> 2) * 64;     // warp M offset: 0 or 64
    const int wn = (wid & 3) * 32;      // warp N offset: 0,32,64,96
    const int mtx = lane >> 3;          // ldmatrix matrix id 0..3
    const int inr = lane & 7;
    // A x4 tile: matrices {m0-7 k0, m8-15 k0, m0-7 k8, m8-15 k8}
    const uint32_t aoff = (uint32_t)((wm + (mtx & 1) * 8 + inr) * ROWP + (mtx >> 1) * 16);
    // B x4 pair: matrices {n0-7 k0, n0-7 k8, n8-15 k0, n8-15 k8}
    const uint32_t boff = (uint32_t)(B_REGION + (wn + (mtx >> 1) * 8 + inr) * ROWP + (mtx & 1) * 16);

    float acc[4][4][4];
#pragma unroll
    for (int i = 0; i < 4; i++)
#pragma unroll
        for (int j = 0; j < 4; j++)
#pragma unroll
            for (int q = 0; q < 4; q++) acc[i][j][q] = 0.f;

    load_stage(0, 0);
    load_stage(1, 1);

    for (int kt = 0; kt < KT; kt++) {
        if (kt == KT - 1) cp_wait<0>(); else cp_wait<1>();
        __syncthreads();   // stage kt visible to all; all warps done with stage kt-1
        if (kt + 2 < KT) load_stage(kt + 2, (kt + 2) % NSTAGE);

        const uint32_t sb = dynb + (uint32_t)(kt % NSTAGE) * STAGE_SZ;
#pragma unroll
        for (int ks = 0; ks < 4; ks++) {
            uint32_t ah[4][4], al[4][4], bh[2][4], bl[2][4];
#pragma unroll
            for (int mt = 0; mt < 4; mt++) {
                uint32_t a = sb + aoff + (uint32_t)(mt * 16 * ROWP + ks * 32);
                ldsm_x4(ah[mt][0], ah[mt][1], ah[mt][2], ah[mt][3], a);
                ldsm_x4(al[mt][0], al[mt][1], al[mt][2], al[mt][3], a + 128 * ROWP);
            }
#pragma unroll
            for (int np = 0; np < 2; np++) {
                uint32_t b = sb + boff + (uint32_t)(np * 16 * ROWP + ks * 32);
                ldsm_x4(bh[np][0], bh[np][1], bh[np][2], bh[np][3], b);
                ldsm_x4(bl[np][0], bl[np][1], bl[np][2], bl[np][3], b + 128 * ROWP);
            }
#pragma unroll
            for (int mt = 0; mt < 4; mt++)
#pragma unroll
                for (int nt = 0; nt < 4; nt++) {
                    const int np = nt >> 1, h2 = (nt & 1) * 2;
                    mma_bf16(acc[mt][nt], ah[mt], bh[np][h2], bh[np][h2 + 1]);
                    mma_bf16(acc[mt][nt], ah[mt], bl[np][h2], bl[np][h2 + 1]);
                    mma_bf16(acc[mt][nt], al[mt], bh[np][h2], bh[np][h2 + 1]);
                }
        }
    }

    // ---- epilogue ----
    const int erow = m0 + wm + (lane >> 2);
    const int ecol = n0 + wn + 2 * (lane & 3);
#pragma unroll
    for (int mt = 0; mt < 4; mt++) {
#pragma unroll
        for (int nt = 0; nt < 4; nt++) {
            const int col = ecol + nt * 8;
            const float bs0 = sbias[col - n0], bs1 = sbias[col - n0 + 1];
#pragma unroll
            for (int hrow = 0; hrow < 2; hrow++) {
                const int row = erow + mt * 16 + hrow * 8;
                if (row < rend) {
                    float v0 = acc[mt][nt][2 * hrow + 0] + bs0;
                    float v1 = acc[mt][nt][2 * hrow + 1] + bs1;
                    size_t off = (size_t)row * NT + col;
                    if (G == 1) {
                        v0 = fmaxf(v0, 0.f);
                        v1 = fmaxf(v1, 0.f);
                        __nv_bfloat16 h0 = __float2bfloat16(v0);
                        __nv_bfloat16 h1 = __float2bfloat16(v1);
                        __nv_bfloat16 l0 = __float2bfloat16(v0 - __bfloat162float(h0));
                        __nv_bfloat16 l1 = __float2bfloat16(v1 - __bfloat162float(h1));
                        *(uint32_t*)(g_hhi + off) = bpack(h0, h1);
                        *(uint32_t*)(g_hlo + off) = bpack(l0, l1);
                    } else {
                        float2 o; o.x = v0; o.y = v1;
                        *(float2*)(g_partial + off) = o;
                    }
                }
            }
        }
    }
}

// ---------------- combine -----------------------------------------------------
__global__ __launch_bounds__(256) void combine_kernel(float* __restrict__ out) {
    int idx = blockIdx.x * blockDim.x + threadIdx.x;
    int n = idx >> 8;
    int cc = (idx & 255) << 2;
    if (n >= N_TOK) return;
    float w0 = g_w_of[2*n+0], w1 = g_w_of[2*n+1];
    int   r0 = g_token_row[2*n+0], r1 = g_token_row[2*n+1];
    float4 p0 = *(const float4*)(g_partial + (size_t)r0 * D_OUTF + cc);
    float4 p1 = *(const float4*)(g_partial + (size_t)r1 * D_OUTF + cc);
    float4 o;
    o.x = w0*p0.x + w1*p1.x;  o.y = w0*p0.y + w1*p1.y;
    o.z = w0*p0.z + w1*p1.z;  o.w = w0*p0.w + w1*p1.w;
    *(float4*)(out + (size_t)n * D_OUTF + cc) = o;
}

// ---------------- launcher ----------------------------------------------------
extern "C" void kernel_launch(void* const* d_in, const int* in_sizes, int n_in,
                              void* d_out, int out_size) {
    const float* x  = (const float*)d_in[0];
    const float* W1 = (const float*)d_in[1];
    const float* b1 = (const float*)d_in[2];
    const float* W2 = (const float*)d_in[3];
    const float* b2 = (const float*)d_in[4];
    const float* Wg = (const float*)d_in[5];
    const float* bg = (const float*)d_in[6];
    float* out = (float*)d_out;

    cudaFuncSetAttribute(gemm_kernel<1>, cudaFuncAttributeMaxDynamicSharedMemorySize, SMEM_DYN);
    cudaFuncSetAttribute(gemm_kernel<2>, cudaFuncAttributeMaxDynamicSharedMemorySize, SMEM_DYN);

    reset_kernel<<<1, 32>>>();
    gating_kernel<<<N_TOK / 8, 256>>>(x, Wg, bg);
    scan_kernel<<<1, 1>>>();
    place_kernel<<<N_TOK / 256, 256>>>();

    cvtx_kernel<<<(N_TOK * D_INF / 4) / 256, 256>>>(x);
    tpose_kernel<D_INF,  D_HIDF, 1><<<dim3(D_HIDF/32, D_INF/32,  NE), dim3(32, 8)>>>(W1);
    tpose_kernel<D_HIDF, D_OUTF, 2><<<dim3(D_OUTF/32, D_HIDF/32, NE), dim3(32, 8)>>>(W2);

    gemm_kernel<1><<<dim3(D_HIDF/128, 64, NE), 256, SMEM_DYN>>>(b1);
    gemm_kernel<2><<<dim3(D_OUTF/128, 64, NE), 256, SMEM_DYN>>>(b2);

    combine_kernel<<<(N_TOK * D_OUTF / 4) / 256, 256>>>(out);
}

// round 8
// speedup vs baseline: 1.7042x; 1.0297x over previous
#include <cuda_runtime.h>
#include <cuda_bf16.h>
#include <math.h>
#include <stdint.h>

// Problem constants
#define N_TOK  8192
#define D_INF  1024
#define D_HIDF 4096
#define D_OUTF 1024
#define NE     8
#define TOPK   2
#define NROWS  (N_TOK * TOPK)

// ---------------- scratch (__device__ globals; allocation-free rule) --------
__device__ __align__(256) __nv_bfloat16 g_xhi[(size_t)N_TOK * D_INF];
__device__ __align__(256) __nv_bfloat16 g_xlo[(size_t)N_TOK * D_INF];
__device__ __align__(256) __nv_bfloat16 g_w1thi[(size_t)NE * D_HIDF * D_INF];  // [E][Nhid][Kin]
__device__ __align__(256) __nv_bfloat16 g_w1tlo[(size_t)NE * D_HIDF * D_INF];
__device__ __align__(256) __nv_bfloat16 g_w2thi[(size_t)NE * D_OUTF * D_HIDF]; // [E][Nout][Khid]
__device__ __align__(256) __nv_bfloat16 g_w2tlo[(size_t)NE * D_OUTF * D_HIDF];
__device__ __align__(256) __nv_bfloat16 g_hhi[(size_t)NROWS * D_HIDF];
__device__ __align__(256) __nv_bfloat16 g_hlo[(size_t)NROWS * D_HIDF];
__device__ __align__(256) float g_partial[(size_t)NROWS * D_OUTF];
__device__ int   g_counts[NE];
__device__ int   g_offsets[NE + 1];
__device__ int   g_cursor[NE];
__device__ int   g_row_token[NROWS];
__device__ int   g_token_row[NROWS];
__device__ int   g_e_of[NROWS];
__device__ float g_w_of[NROWS];

// ---------------- PTX helpers (base sm_103 only; NO 'a' features) -----------
__device__ __forceinline__ uint32_t smem_u32(const void* p) {
    uint32_t a;
    asm("{ .reg .u64 t; cvta.to.shared.u64 t, %1; cvt.u32.u64 %0, t; }"
        : "=r"(a) : "l"(p));
    return a;
}
__device__ __forceinline__ void cp16(uint32_t dst, const void* src) {
    unsigned long long g = (unsigned long long)__cvta_generic_to_global(src);
    asm volatile("cp.async.cg.shared.global [%0], [%1], 16;" :: "r"(dst), "l"(g));
}
#define CP_COMMIT() asm volatile("cp.async.commit_group;" ::: "memory")
template <int Np> __device__ __forceinline__ void cp_wait() {
    asm volatile("cp.async.wait_group %0;" :: "n"(Np) : "memory");
}
__device__ __forceinline__ void ldsm_x4(uint32_t& r0, uint32_t& r1, uint32_t& r2,
                                        uint32_t& r3, uint32_t addr) {
    asm volatile("ldmatrix.sync.aligned.m8n8.x4.shared.b16 {%0,%1,%2,%3}, [%4];"
                 : "=r"(r0), "=r"(r1), "=r"(r2), "=r"(r3) : "r"(addr));
}
__device__ __forceinline__ void mma_bf16(float* c, const uint32_t* a, uint32_t b0,
                                         uint32_t b1) {
    asm volatile(
        "mma.sync.aligned.m16n8k16.row.col.f32.bf16.bf16.f32 "
        "{%0,%1,%2,%3}, {%4,%5,%6,%7}, {%8,%9}, {%0,%1,%2,%3};"
        : "+f"(c[0]), "+f"(c[1]), "+f"(c[2]), "+f"(c[3])
        : "r"(a[0]), "r"(a[1]), "r"(a[2]), "r"(a[3]), "r"(b0), "r"(b1));
}
__device__ __forceinline__ uint32_t bpack(__nv_bfloat16 a, __nv_bfloat16 b) {
    return (uint32_t)__bfloat16_as_ushort(a) | ((uint32_t)__bfloat16_as_ushort(b) << 16);
}

// ---------------- kernel 0: reset --------------------------------------------
__global__ void reset_kernel() {
    int t = threadIdx.x;
    if (t < NE) g_counts[t] = 0;
}

// ---------------- kernel 1: gating -------------------------------------------
__global__ __launch_bounds__(256) void gating_kernel(
    const float* __restrict__ x, const float* __restrict__ Wg,
    const float* __restrict__ bg)
{
    int gwarp = (blockIdx.x * blockDim.x + threadIdx.x) >> 5;
    int lane  = threadIdx.x & 31;
    if (gwarp >= N_TOK) return;
    const float* xr = x + (size_t)gwarp * D_INF;

    float acc[NE];
#pragma unroll
    for (int e = 0; e < NE; e++) acc[e] = 0.f;
    for (int k = lane; k < D_INF; k += 32) {
        float xv = xr[k];
        const float* wgr = Wg + (size_t)k * NE;
#pragma unroll
        for (int e = 0; e < NE; e++) acc[e] = fmaf(xv, wgr[e], acc[e]);
    }
#pragma unroll
    for (int off = 16; off; off >>= 1)
#pragma unroll
        for (int e = 0; e < NE; e++)
            acc[e] += __shfl_xor_sync(0xffffffffu, acc[e], off);

    if (lane == 0) {
        float s[NE];
#pragma unroll
        for (int e = 0; e < NE; e++) s[e] = acc[e] + bg[e];
        float mx = s[0];
#pragma unroll
        for (int e = 1; e < NE; e++) mx = fmaxf(mx, s[e]);
        float p[NE], sum = 0.f;
#pragma unroll
        for (int e = 0; e < NE; e++) { p[e] = expf(s[e] - mx); sum += p[e]; }
        float inv = 1.0f / sum;
#pragma unroll
        for (int e = 0; e < NE; e++) p[e] *= inv;
        int e0 = 0;
#pragma unroll
        for (int e = 1; e < NE; e++) if (s[e] > s[e0]) e0 = e;
        int e1 = (e0 == 0) ? 1 : 0;
#pragma unroll
        for (int e = 0; e < NE; e++) if (e != e0 && s[e] > s[e1]) e1 = e;
        float denom = p[e0] + p[e1] + 1e-8f;
        int n = gwarp;
        g_e_of[2*n+0] = e0;  g_e_of[2*n+1] = e1;
        g_w_of[2*n+0] = p[e0] / denom;  g_w_of[2*n+1] = p[e1] / denom;
        atomicAdd(&g_counts[e0], 1);
        atomicAdd(&g_counts[e1], 1);
    }
}

// ---------------- kernel 2/3: scan + placement -------------------------------
__global__ void scan_kernel() {
    int o = 0;
#pragma unroll
    for (int e = 0; e < NE; e++) { g_offsets[e] = o; g_cursor[e] = o; o += g_counts[e]; }
    g_offsets[NE] = o;
}
__global__ void place_kernel() {
    int n = blockIdx.x * blockDim.x + threadIdx.x;
    if (n >= N_TOK) return;
#pragma unroll
    for (int s = 0; s < TOPK; s++) {
        int e = g_e_of[2*n+s];
        int r = atomicAdd(&g_cursor[e], 1);
        g_row_token[r] = n;
        g_token_row[2*n+s] = r;
    }
}

// ---------------- prepass: x -> bf16 hi/lo -----------------------------------
__global__ __launch_bounds__(256) void cvtx_kernel(const float* __restrict__ x) {
    size_t i = ((size_t)blockIdx.x * 256 + threadIdx.x) * 4;
    float4 v = *(const float4*)(x + i);
    __nv_bfloat16 h0 = __float2bfloat16(v.x), h1 = __float2bfloat16(v.y);
    __nv_bfloat16 h2 = __float2bfloat16(v.z), h3 = __float2bfloat16(v.w);
    __nv_bfloat16 l0 = __float2bfloat16(v.x - __bfloat162float(h0));
    __nv_bfloat16 l1 = __float2bfloat16(v.y - __bfloat162float(h1));
    __nv_bfloat16 l2 = __float2bfloat16(v.z - __bfloat162float(h2));
    __nv_bfloat16 l3 = __float2bfloat16(v.w - __bfloat162float(h3));
    uint2 hh, ll;
    hh.x = bpack(h0, h1); hh.y = bpack(h2, h3);
    ll.x = bpack(l0, l1); ll.y = bpack(l2, l3);
    *(uint2*)(g_xhi + i) = hh;
    *(uint2*)(g_xlo + i) = ll;
}

// ---------------- prepass: W [E][K][N] -> WT hi/lo [E][N][K] ------------------
template <int K, int N, int WCH>
__global__ void tpose_kernel(const float* __restrict__ Wsrc) {
    __shared__ float t[32][33];
    int e  = blockIdx.z;
    int n0 = blockIdx.x * 32, k0 = blockIdx.y * 32;
    int tx = threadIdx.x, ty = threadIdx.y;  // 32 x 8
    const float* src = Wsrc + ((size_t)e * K + k0) * N + n0;
#pragma unroll
    for (int i = 0; i < 4; i++)
        t[ty + 8*i][tx] = src[(size_t)(ty + 8*i) * N + tx];
    __syncthreads();
    __nv_bfloat16* Thi = (WCH == 1) ? g_w1thi : g_w2thi;
    __nv_bfloat16* Tlo = (WCH == 1) ? g_w1tlo : g_w2tlo;
    size_t ob = ((size_t)e * N + n0) * K + k0;
#pragma unroll
    for (int i = 0; i < 4; i++) {
        float v = t[tx][ty + 8*i];
        __nv_bfloat16 h = __float2bfloat16(v);
        Thi[ob + (size_t)(ty + 8*i) * K + tx] = h;
        Tlo[ob + (size_t)(ty + 8*i) * K + tx] = __float2bfloat16(v - __bfloat162float(h));
    }
}

// ---------------- grouped HMMA GEMM (bf16 hi/lo 3-pass) -----------------------
// BM=256, BN=128, BK=64, 256 threads (8 warps, warp tile 64x64), 2-stage cp.async.
// Stage rows: [0,256)=Ahi, [256,512)=Alo, [512,640)=Bhi, [640,768)=Blo; 144B pitch.
#define ROWP       144
#define STAGE_ROWS 768
#define STAGE_SZ   (STAGE_ROWS * ROWP)      // 110592
#define SMEM_DYN   (2 * STAGE_SZ + 256)     // 221440

template <int G>
__global__ __launch_bounds__(256, 1) void gemm_kernel(const float* __restrict__ bias_g) {
    constexpr int KD = (G == 1) ? D_INF : D_HIDF;
    constexpr int NT = (G == 1) ? D_HIDF : D_OUTF;
    constexpr int KT = KD / 64;

    const int e    = blockIdx.z;
    const int rbeg = g_offsets[e];
    const int rend = g_offsets[e + 1];
    const int m0   = rbeg + blockIdx.y * 256;
    if (m0 >= rend) return;
    const int n0   = blockIdx.x * 128;

    __shared__ float sbias[128];
    extern __shared__ char dsm[];
    const uint32_t dynb = (smem_u32(dsm) + 127u) & ~127u;

    const int tid  = threadIdx.x;
    const int wid  = tid >> 5;
    const int lane = tid & 31;

    if (tid < 128) sbias[tid] = bias_g[(size_t)e * NT + n0 + tid];

    const __nv_bfloat16* ahi_g = (G == 1) ? g_xhi : g_hhi;
    const __nv_bfloat16* alo_g = (G == 1) ? g_xlo : g_hlo;
    const __nv_bfloat16* bhi_g = (G == 1) ? g_w1thi : g_w2thi;
    const __nv_bfloat16* blo_g = (G == 1) ? g_w1tlo : g_w2tlo;

    // ---- loader geometry: 3 rows per thread (768 rows / 256 threads) --------
    const __nv_bfloat16* gsrc[3];
    uint32_t dstoff[3];
#pragma unroll
    for (int q = 0; q < 3; q++) {
        const int r = tid + 256 * q;        // 0..767
        if (r < 512) {                      // A rows (hi then lo)
            int gr = m0 + (r & 255);
            if (gr >= rend) gr = rbeg;      // valid garbage row; epilogue masks
            size_t rowb = (G == 1) ? (size_t)g_row_token[gr] * KD : (size_t)gr * KD;
            gsrc[q] = ((r < 256) ? ahi_g : alo_g) + rowb;
        } else {                            // B rows (hi then lo)
            const int br = r - 512;         // 0..255
            size_t rowb = ((size_t)e * NT + n0 + (br & 127)) * KD;
            gsrc[q] = ((br < 128) ? bhi_g : blo_g) + rowb;
        }
        dstoff[q] = (uint32_t)(r * ROWP);
    }

    auto load_stage = [&](int kt, int stg) {
        const uint32_t sb = dynb + (uint32_t)stg * STAGE_SZ;
        const int k0 = kt * 64;
#pragma unroll
        for (int q = 0; q < 3; q++) {
            const __nv_bfloat16* src = gsrc[q] + k0;
            const uint32_t dst = sb + dstoff[q];
#pragma unroll
            for (int c = 0; c < 8; c++) cp16(dst + c * 16, src + c * 8);
        }
        CP_COMMIT();
    };

    // ---- fragment address bases ----
    const int wm = (wid >> 1) * 64;     // warp M offset: 0,64,128,192
    const int wn = (wid & 1) * 64;      // warp N offset: 0,64
    const int mtx = lane >> 3;          // ldmatrix matrix id 0..3
    const int inr = lane & 7;
    // A x4 tile: matrices {m0-7 k0, m8-15 k0, m0-7 k8, m8-15 k8}
    const uint32_t aoff_hi = (uint32_t)((wm + (mtx & 1) * 8 + inr) * ROWP + (mtx >> 1) * 16);
    const uint32_t aoff_lo = aoff_hi + 256 * ROWP;
    // B x4 tile: matrices {n0-7 k0, n0-7 k8, n8-15 k0, n8-15 k8}
    const uint32_t boff_hi = (uint32_t)((512 + wn + (mtx >> 1) * 8 + inr) * ROWP + (mtx & 1) * 16);
    const uint32_t boff_lo = boff_hi + 128 * ROWP;

    float acc[4][8][4];
#pragma unroll
    for (int i = 0; i < 4; i++)
#pragma unroll
        for (int j = 0; j < 8; j++)
#pragma unroll
            for (int q = 0; q < 4; q++) acc[i][j][q] = 0.f;

    load_stage(0, 0);

    for (int kt = 0; kt < KT; kt++) {
        cp_wait<0>();
        __syncthreads();   // stage kt visible; prior stage's consumers done
        if (kt + 1 < KT) load_stage(kt + 1, (kt + 1) & 1);

        const uint32_t sb = dynb + (uint32_t)(kt & 1) * STAGE_SZ;
#pragma unroll
        for (int ks = 0; ks < 4; ks++) {
            uint32_t ah[4][4], al[4][4];
#pragma unroll
            for (int mt = 0; mt < 4; mt++) {
                const uint32_t ao = (uint32_t)(mt * 16 * ROWP + ks * 32);
                ldsm_x4(ah[mt][0], ah[mt][1], ah[mt][2], ah[mt][3], sb + aoff_hi + ao);
                ldsm_x4(al[mt][0], al[mt][1], al[mt][2], al[mt][3], sb + aoff_lo + ao);
            }
#pragma unroll
            for (int g = 0; g < 4; g++) {
                const uint32_t go = (uint32_t)(g * 16 * ROWP + ks * 32);
                uint32_t bh[4];
                ldsm_x4(bh[0], bh[1], bh[2], bh[3], sb + boff_hi + go);
#pragma unroll
                for (int mt = 0; mt < 4; mt++) {
                    mma_bf16(acc[mt][2*g+0], ah[mt], bh[0], bh[1]);
                    mma_bf16(acc[mt][2*g+1], ah[mt], bh[2], bh[3]);
                    mma_bf16(acc[mt][2*g+0], al[mt], bh[0], bh[1]);
                    mma_bf16(acc[mt][2*g+1], al[mt], bh[2], bh[3]);
                }
                uint32_t bl[4];
                ldsm_x4(bl[0], bl[1], bl[2], bl[3], sb + boff_lo + go);
#pragma unroll
                for (int mt = 0; mt < 4; mt++) {
                    mma_bf16(acc[mt][2*g+0], ah[mt], bl[0], bl[1]);
                    mma_bf16(acc[mt][2*g+1], ah[mt], bl[2], bl[3]);
                }
            }
        }
    }

    // ---- epilogue ----
    const int erow = m0 + wm + (lane >> 2);
    const int ecol = n0 + wn + 2 * (lane & 3);
#pragma unroll
    for (int mt = 0; mt < 4; mt++) {
#pragma unroll
        for (int nt = 0; nt < 8; nt++) {
            const int col = ecol + nt * 8;
            const float bs0 = sbias[col - n0], bs1 = sbias[col - n0 + 1];
#pragma unroll
            for (int hrow = 0; hrow < 2; hrow++) {
                const int row = erow + mt * 16 + hrow * 8;
                if (row < rend) {
                    float v0 = acc[mt][nt][2 * hrow + 0] + bs0;
                    float v1 = acc[mt][nt][2 * hrow + 1] + bs1;
                    size_t off = (size_t)row * NT + col;
                    if (G == 1) {
                        v0 = fmaxf(v0, 0.f);
                        v1 = fmaxf(v1, 0.f);
                        __nv_bfloat16 h0 = __float2bfloat16(v0);
                        __nv_bfloat16 h1 = __float2bfloat16(v1);
                        __nv_bfloat16 l0 = __float2bfloat16(v0 - __bfloat162float(h0));
                        __nv_bfloat16 l1 = __float2bfloat16(v1 - __bfloat162float(h1));
                        *(uint32_t*)(g_hhi + off) = bpack(h0, h1);
                        *(uint32_t*)(g_hlo + off) = bpack(l0, l1);
                    } else {
                        float2 o; o.x = v0; o.y = v1;
                        *(float2*)(g_partial + off) = o;
                    }
                }
            }
        }
    }
}

// ---------------- combine -----------------------------------------------------
__global__ __launch_bounds__(256) void combine_kernel(float* __restrict__ out) {
    int idx = blockIdx.x * blockDim.x + threadIdx.x;
    int n = idx >> 8;
    int cc = (idx & 255) << 2;
    if (n >= N_TOK) return;
    float w0 = g_w_of[2*n+0], w1 = g_w_of[2*n+1];
    int   r0 = g_token_row[2*n+0], r1 = g_token_row[2*n+1];
    float4 p0 = *(const float4*)(g_partial + (size_t)r0 * D_OUTF + cc);
    float4 p1 = *(const float4*)(g_partial + (size_t)r1 * D_OUTF + cc);
    float4 o;
    o.x = w0*p0.x + w1*p1.x;  o.y = w0*p0.y + w1*p1.y;
    o.z = w0*p0.z + w1*p1.z;  o.w = w0*p0.w + w1*p1.w;
    *(float4*)(out + (size_t)n * D_OUTF + cc) = o;
}

// ---------------- launcher ----------------------------------------------------
extern "C" void kernel_launch(void* const* d_in, const int* in_sizes, int n_in,
                              void* d_out, int out_size) {
    const float* x  = (const float*)d_in[0];
    const float* W1 = (const float*)d_in[1];
    const float* b1 = (const float*)d_in[2];
    const float* W2 = (const float*)d_in[3];
    const float* b2 = (const float*)d_in[4];
    const float* Wg = (const float*)d_in[5];
    const float* bg = (const float*)d_in[6];
    float* out = (float*)d_out;

    cudaFuncSetAttribute(gemm_kernel<1>, cudaFuncAttributeMaxDynamicSharedMemorySize, SMEM_DYN);
    cudaFuncSetAttribute(gemm_kernel<2>, cudaFuncAttributeMaxDynamicSharedMemorySize, SMEM_DYN);

    reset_kernel<<<1, 32>>>();
    gating_kernel<<<N_TOK / 8, 256>>>(x, Wg, bg);
    scan_kernel<<<1, 1>>>();
    place_kernel<<<N_TOK / 256, 256>>>();

    cvtx_kernel<<<(N_TOK * D_INF / 4) / 256, 256>>>(x);
    tpose_kernel<D_INF,  D_HIDF, 1><<<dim3(D_HIDF/32, D_INF/32,  NE), dim3(32, 8)>>>(W1);
    tpose_kernel<D_HIDF, D_OUTF, 2><<<dim3(D_OUTF/32, D_HIDF/32, NE), dim3(32, 8)>>>(W2);

    gemm_kernel<1><<<dim3(D_HIDF/128, 64, NE), 256, SMEM_DYN>>>(b1);
    gemm_kernel<2><<<dim3(D_OUTF/128, 64, NE), 256, SMEM_DYN>>>(b2);

    combine_kernel<<<(N_TOK * D_OUTF / 4) / 256, 256>>>(out);
}

// round 9
// speedup vs baseline: 2.1900x; 1.2850x over previous
#include <cuda_runtime.h>
#include <cuda_bf16.h>
#include <cuda_fp16.h>
#include <math.h>
#include <stdint.h>

// Problem constants
#define N_TOK  8192
#define D_INF  1024
#define D_HIDF 4096
#define D_OUTF 1024
#define NE     8
#define TOPK   2
#define NROWS  (N_TOK * TOPK)

// ---------------- scratch (__device__ globals; allocation-free rule) --------
__device__ __align__(256) __half g_xhi[(size_t)N_TOK * D_INF];
__device__ __align__(256) __half g_xlo[(size_t)N_TOK * D_INF];
__device__ __align__(256) __half g_w1t[(size_t)NE * D_HIDF * D_INF];  // [E][Nhid][Kin], fp16 hi only
__device__ __align__(256) __half g_w2t[(size_t)NE * D_OUTF * D_HIDF]; // [E][Nout][Khid]
__device__ __align__(256) __half g_hhi[(size_t)NROWS * D_HIDF];
__device__ __align__(256) __half g_hlo[(size_t)NROWS * D_HIDF];
__device__ __align__(256) float g_partial[(size_t)NROWS * D_OUTF];
__device__ int   g_counts[NE];
__device__ int   g_offsets[NE + 1];
__device__ int   g_cursor[NE];
__device__ int   g_row_token[NROWS];
__device__ int   g_token_row[NROWS];
__device__ int   g_e_of[NROWS];
__device__ float g_w_of[NROWS];

// ---------------- PTX helpers (base sm_103 only; NO 'a' features) -----------
__device__ __forceinline__ uint32_t smem_u32(const void* p) {
    uint32_t a;
    asm("{ .reg .u64 t; cvta.to.shared.u64 t, %1; cvt.u32.u64 %0, t; }"
        : "=r"(a) : "l"(p));
    return a;
}
__device__ __forceinline__ void cp16(uint32_t dst, const void* src) {
    unsigned long long g = (unsigned long long)__cvta_generic_to_global(src);
    asm volatile("cp.async.cg.shared.global [%0], [%1], 16;" :: "r"(dst), "l"(g));
}
#define CP_COMMIT() asm volatile("cp.async.commit_group;" ::: "memory")
template <int Np> __device__ __forceinline__ void cp_wait() {
    asm volatile("cp.async.wait_group %0;" :: "n"(Np) : "memory");
}
__device__ __forceinline__ void ldsm_x4(uint32_t& r0, uint32_t& r1, uint32_t& r2,
                                        uint32_t& r3, uint32_t addr) {
    asm volatile("ldmatrix.sync.aligned.m8n8.x4.shared.b16 {%0,%1,%2,%3}, [%4];"
                 : "=r"(r0), "=r"(r1), "=r"(r2), "=r"(r3) : "r"(addr));
}
__device__ __forceinline__ void mma_f16(float* c, const uint32_t* a, uint32_t b0,
                                        uint32_t b1) {
    asm volatile(
        "mma.sync.aligned.m16n8k16.row.col.f32.f16.f16.f32 "
        "{%0,%1,%2,%3}, {%4,%5,%6,%7}, {%8,%9}, {%0,%1,%2,%3};"
        : "+f"(c[0]), "+f"(c[1]), "+f"(c[2]), "+f"(c[3])
        : "r"(a[0]), "r"(a[1]), "r"(a[2]), "r"(a[3]), "r"(b0), "r"(b1));
}
__device__ __forceinline__ uint32_t hpack(__half a, __half b) {
    return (uint32_t)__half_as_ushort(a) | ((uint32_t)__half_as_ushort(b) << 16);
}

// ---------------- kernel 0: reset --------------------------------------------
__global__ void reset_kernel() {
    int t = threadIdx.x;
    if (t < NE) g_counts[t] = 0;
}

// ---------------- kernel 1: gating -------------------------------------------
__global__ __launch_bounds__(256) void gating_kernel(
    const float* __restrict__ x, const float* __restrict__ Wg,
    const float* __restrict__ bg)
{
    int gwarp = (blockIdx.x * blockDim.x + threadIdx.x) >> 5;
    int lane  = threadIdx.x & 31;
    if (gwarp >= N_TOK) return;
    const float* xr = x + (size_t)gwarp * D_INF;

    float acc[NE];
#pragma unroll
    for (int e = 0; e < NE; e++) acc[e] = 0.f;
    for (int k = lane; k < D_INF; k += 32) {
        float xv = xr[k];
        const float* wgr = Wg + (size_t)k * NE;
#pragma unroll
        for (int e = 0; e < NE; e++) acc[e] = fmaf(xv, wgr[e], acc[e]);
    }
#pragma unroll
    for (int off = 16; off; off >>= 1)
#pragma unroll
        for (int e = 0; e < NE; e++)
            acc[e] += __shfl_xor_sync(0xffffffffu, acc[e], off);

    if (lane == 0) {
        float s[NE];
#pragma unroll
        for (int e = 0; e < NE; e++) s[e] = acc[e] + bg[e];
        float mx = s[0];
#pragma unroll
        for (int e = 1; e < NE; e++) mx = fmaxf(mx, s[e]);
        float p[NE], sum = 0.f;
#pragma unroll
        for (int e = 0; e < NE; e++) { p[e] = expf(s[e] - mx); sum += p[e]; }
        float inv = 1.0f / sum;
#pragma unroll
        for (int e = 0; e < NE; e++) p[e] *= inv;
        int e0 = 0;
#pragma unroll
        for (int e = 1; e < NE; e++) if (s[e] > s[e0]) e0 = e;
        int e1 = (e0 == 0) ? 1 : 0;
#pragma unroll
        for (int e = 0; e < NE; e++) if (e != e0 && s[e] > s[e1]) e1 = e;
        float denom = p[e0] + p[e1] + 1e-8f;
        int n = gwarp;
        g_e_of[2*n+0] = e0;  g_e_of[2*n+1] = e1;
        g_w_of[2*n+0] = p[e0] / denom;  g_w_of[2*n+1] = p[e1] / denom;
        atomicAdd(&g_counts[e0], 1);
        atomicAdd(&g_counts[e1], 1);
    }
}

// ---------------- kernel 2/3: scan + placement -------------------------------
__global__ void scan_kernel() {
    int o = 0;
#pragma unroll
    for (int e = 0; e < NE; e++) { g_offsets[e] = o; g_cursor[e] = o; o += g_counts[e]; }
    g_offsets[NE] = o;
}
__global__ void place_kernel() {
    int n = blockIdx.x * blockDim.x + threadIdx.x;
    if (n >= N_TOK) return;
#pragma unroll
    for (int s = 0; s < TOPK; s++) {
        int e = g_e_of[2*n+s];
        int r = atomicAdd(&g_cursor[e], 1);
        g_row_token[r] = n;
        g_token_row[2*n+s] = r;
    }
}

// ---------------- prepass: x -> fp16 hi/lo -----------------------------------
__global__ __launch_bounds__(256) void cvtx_kernel(const float* __restrict__ x) {
    size_t i = ((size_t)blockIdx.x * 256 + threadIdx.x) * 4;
    float4 v = *(const float4*)(x + i);
    __half h0 = __float2half_rn(v.x), h1 = __float2half_rn(v.y);
    __half h2 = __float2half_rn(v.z), h3 = __float2half_rn(v.w);
    __half l0 = __float2half_rn(v.x - __half2float(h0));
    __half l1 = __float2half_rn(v.y - __half2float(h1));
    __half l2 = __float2half_rn(v.z - __half2float(h2));
    __half l3 = __float2half_rn(v.w - __half2float(h3));
    uint2 hh, ll;
    hh.x = hpack(h0, h1); hh.y = hpack(h2, h3);
    ll.x = hpack(l0, l1); ll.y = hpack(l2, l3);
    *(uint2*)(g_xhi + i) = hh;
    *(uint2*)(g_xlo + i) = ll;
}

// ---------------- prepass: W [E][K][N] -> WT fp16 [E][N][K] -------------------
template <int K, int N, int WCH>
__global__ void tpose_kernel(const float* __restrict__ Wsrc) {
    __shared__ float t[32][33];
    int e  = blockIdx.z;
    int n0 = blockIdx.x * 32, k0 = blockIdx.y * 32;
    int tx = threadIdx.x, ty = threadIdx.y;  // 32 x 8
    const float* src = Wsrc + ((size_t)e * K + k0) * N + n0;
#pragma unroll
    for (int i = 0; i < 4; i++)
        t[ty + 8*i][tx] = src[(size_t)(ty + 8*i) * N + tx];
    __syncthreads();
    __half* T = (WCH == 1) ? g_w1t : g_w2t;
    size_t ob = ((size_t)e * N + n0) * K + k0;
#pragma unroll
    for (int i = 0; i < 4; i++) {
        float v = t[tx][ty + 8*i];
        T[ob + (size_t)(ty + 8*i) * K + tx] = __float2half_rn(v);
    }
}

// ---------------- grouped HMMA GEMM (fp16 hi/lo 2-pass) -----------------------
// BM=256, BN=128, BK=64, 256 threads (8 warps, warp tile 64x64), 2-stage cp.async.
// Stage rows: [0,256)=Ahi, [256,512)=Alo, [512,640)=B; 144B pitch.
#define ROWP       144
#define STAGE_ROWS 640
#define STAGE_SZ   (STAGE_ROWS * ROWP)      // 92160
#define SMEM_DYN   (2 * STAGE_SZ + 256)     // 184576

template <int G>
__global__ __launch_bounds__(256, 1) void gemm_kernel(const float* __restrict__ bias_g) {
    constexpr int KD = (G == 1) ? D_INF : D_HIDF;
    constexpr int NT = (G == 1) ? D_HIDF : D_OUTF;
    constexpr int KT = KD / 64;

    const int e    = blockIdx.z;
    const int rbeg = g_offsets[e];
    const int rend = g_offsets[e + 1];
    const int m0   = rbeg + blockIdx.y * 256;
    if (m0 >= rend) return;
    const int n0   = blockIdx.x * 128;

    __shared__ float sbias[128];
    extern __shared__ char dsm[];
    const uint32_t dynb = (smem_u32(dsm) + 127u) & ~127u;

    const int tid  = threadIdx.x;
    const int wid  = tid >> 5;
    const int lane = tid & 31;

    if (tid < 128) sbias[tid] = bias_g[(size_t)e * NT + n0 + tid];

    const __half* ahi_g = (G == 1) ? g_xhi : g_hhi;
    const __half* alo_g = (G == 1) ? g_xlo : g_hlo;
    const __half* b_g   = (G == 1) ? g_w1t : g_w2t;

    // ---- loader geometry: 640 rows / 256 threads: 2 rows each + 3rd for tid<128
    const __half* gsrc[3];
    uint32_t dstoff[3];
    bool has3 = (tid < 128);
#pragma unroll
    for (int q = 0; q < 3; q++) {
        const int r = tid + 256 * q;        // 0..767 (r>=640 unused)
        if (r < 512) {                      // A rows (hi then lo)
            int gr = m0 + (r & 255);
            if (gr >= rend) gr = rbeg;      // valid garbage row; epilogue masks
            size_t rowb = (G == 1) ? (size_t)g_row_token[gr] * KD : (size_t)gr * KD;
            gsrc[q] = ((r < 256) ? ahi_g : alo_g) + rowb;
            dstoff[q] = (uint32_t)(r * ROWP);
        } else if (r < 640) {               // B rows
            const int br = r - 512;         // 0..127
            size_t rowb = ((size_t)e * NT + n0 + br) * KD;
            gsrc[q] = b_g + rowb;
            dstoff[q] = (uint32_t)(r * ROWP);
        } else {
            gsrc[q] = gsrc[0];              // unused (guarded by has3)
            dstoff[q] = dstoff[0];
        }
    }

    auto load_stage = [&](int kt, int stg) {
        const uint32_t sb = dynb + (uint32_t)stg * STAGE_SZ;
        const int k0 = kt * 64;
#pragma unroll
        for (int q = 0; q < 3; q++) {
            if (q == 2 && !has3) break;
            const __half* src = gsrc[q] + k0;
            const uint32_t dst = sb + dstoff[q];
#pragma unroll
            for (int c = 0; c < 8; c++) cp16(dst + c * 16, src + c * 8);
        }
        CP_COMMIT();
    };

    // ---- fragment address bases ----
    const int wm = (wid >> 1) * 64;     // warp M offset: 0,64,128,192
    const int wn = (wid & 1) * 64;      // warp N offset: 0,64
    const int mtx = lane >> 3;          // ldmatrix matrix id 0..3
    const int inr = lane & 7;
    // A x4 tile: matrices {m0-7 k0, m8-15 k0, m0-7 k8, m8-15 k8}
    const uint32_t aoff_hi = (uint32_t)((wm + (mtx & 1) * 8 + inr) * ROWP + (mtx >> 1) * 16);
    const uint32_t aoff_lo = aoff_hi + 256 * ROWP;
    // B x4 tile: matrices {n0-7 k0, n0-7 k8, n8-15 k0, n8-15 k8}
    const uint32_t boff = (uint32_t)((512 + wn + (mtx >> 1) * 8 + inr) * ROWP + (mtx & 1) * 16);

    float acc[4][8][4];
#pragma unroll
    for (int i = 0; i < 4; i++)
#pragma unroll
        for (int j = 0; j < 8; j++)
#pragma unroll
            for (int q = 0; q < 4; q++) acc[i][j][q] = 0.f;

    load_stage(0, 0);

    for (int kt = 0; kt < KT; kt++) {
        cp_wait<0>();
        __syncthreads();   // stage kt visible; prior stage's consumers done
        if (kt + 1 < KT) load_stage(kt + 1, (kt + 1) & 1);

        const uint32_t sb = dynb + (uint32_t)(kt & 1) * STAGE_SZ;
#pragma unroll
        for (int ks = 0; ks < 4; ks++) {
            uint32_t ah[4][4], al[4][4];
#pragma unroll
            for (int mt = 0; mt < 4; mt++) {
                const uint32_t ao = (uint32_t)(mt * 16 * ROWP + ks * 32);
                ldsm_x4(ah[mt][0], ah[mt][1], ah[mt][2], ah[mt][3], sb + aoff_hi + ao);
                ldsm_x4(al[mt][0], al[mt][1], al[mt][2], al[mt][3], sb + aoff_lo + ao);
            }
#pragma unroll
            for (int g = 0; g < 4; g++) {
                const uint32_t go = (uint32_t)(g * 16 * ROWP + ks * 32);
                uint32_t bh[4];
                ldsm_x4(bh[0], bh[1], bh[2], bh[3], sb + boff + go);
#pragma unroll
                for (int mt = 0; mt < 4; mt++) {
                    mma_f16(acc[mt][2*g+0], ah[mt], bh[0], bh[1]);
                    mma_f16(acc[mt][2*g+1], ah[mt], bh[2], bh[3]);
                    mma_f16(acc[mt][2*g+0], al[mt], bh[0], bh[1]);
                    mma_f16(acc[mt][2*g+1], al[mt], bh[2], bh[3]);
                }
            }
        }
    }

    // ---- epilogue ----
    const int erow = m0 + wm + (lane >> 2);
    const int ecol = n0 + wn + 2 * (lane & 3);
#pragma unroll
    for (int mt = 0; mt < 4; mt++) {
#pragma unroll
        for (int nt = 0; nt < 8; nt++) {
            const int col = ecol + nt * 8;
            const float bs0 = sbias[col - n0], bs1 = sbias[col - n0 + 1];
#pragma unroll
            for (int hrow = 0; hrow < 2; hrow++) {
                const int row = erow + mt * 16 + hrow * 8;
                if (row < rend) {
                    float v0 = acc[mt][nt][2 * hrow + 0] + bs0;
                    float v1 = acc[mt][nt][2 * hrow + 1] + bs1;
                    size_t off = (size_t)row * NT + col;
                    if (G == 1) {
                        v0 = fmaxf(v0, 0.f);
                        v1 = fmaxf(v1, 0.f);
                        __half h0 = __float2half_rn(v0);
                        __half h1 = __float2half_rn(v1);
                        __half l0 = __float2half_rn(v0 - __half2float(h0));
                        __half l1 = __float2half_rn(v1 - __half2float(h1));
                        *(uint32_t*)(g_hhi + off) = hpack(h0, h1);
                        *(uint32_t*)(g_hlo + off) = hpack(l0, l1);
                    } else {
                        float2 o; o.x = v0; o.y = v1;
                        *(float2*)(g_partial + off) = o;
                    }
                }
            }
        }
    }
}

// ---------------- combine -----------------------------------------------------
__global__ __launch_bounds__(256) void combine_kernel(float* __restrict__ out) {
    int idx = blockIdx.x * blockDim.x + threadIdx.x;
    int n = idx >> 8;
    int cc = (idx & 255) << 2;
    if (n >= N_TOK) return;
    float w0 = g_w_of[2*n+0], w1 = g_w_of[2*n+1];
    int   r0 = g_token_row[2*n+0], r1 = g_token_row[2*n+1];
    float4 p0 = *(const float4*)(g_partial + (size_t)r0 * D_OUTF + cc);
    float4 p1 = *(const float4*)(g_partial + (size_t)r1 * D_OUTF + cc);
    float4 o;
    o.x = w0*p0.x + w1*p1.x;  o.y = w0*p0.y + w1*p1.y;
    o.z = w0*p0.z + w1*p1.z;  o.w = w0*p0.w + w1*p1.w;
    *(float4*)(out + (size_t)n * D_OUTF + cc) = o;
}

// ---------------- launcher ----------------------------------------------------
extern "C" void kernel_launch(void* const* d_in, const int* in_sizes, int n_in,
                              void* d_out, int out_size) {
    const float* x  = (const float*)d_in[0];
    const float* W1 = (const float*)d_in[1];
    const float* b1 = (const float*)d_in[2];
    const float* W2 = (const float*)d_in[3];
    const float* b2 = (const float*)d_in[4];
    const float* Wg = (const float*)d_in[5];
    const float* bg = (const float*)d_in[6];
    float* out = (float*)d_out;

    cudaFuncSetAttribute(gemm_kernel<1>, cudaFuncAttributeMaxDynamicSharedMemorySize, SMEM_DYN);
    cudaFuncSetAttribute(gemm_kernel<2>, cudaFuncAttributeMaxDynamicSharedMemorySize, SMEM_DYN);

    reset_kernel<<<1, 32>>>();
    gating_kernel<<<N_TOK / 8, 256>>>(x, Wg, bg);
    scan_kernel<<<1, 1>>>();
    place_kernel<<<N_TOK / 256, 256>>>();

    cvtx_kernel<<<(N_TOK * D_INF / 4) / 256, 256>>>(x);
    tpose_kernel<D_INF,  D_HIDF, 1><<<dim3(D_HIDF/32, D_INF/32,  NE), dim3(32, 8)>>>(W1);
    tpose_kernel<D_HIDF, D_OUTF, 2><<<dim3(D_OUTF/32, D_HIDF/32, NE), dim3(32, 8)>>>(W2);

    gemm_kernel<1><<<dim3(D_HIDF/128, 64, NE), 256, SMEM_DYN>>>(b1);
    gemm_kernel<2><<<dim3(D_OUTF/128, 64, NE), 256, SMEM_DYN>>>(b2);

    combine_kernel<<<(N_TOK * D_OUTF / 4) / 256, 256>>>(out);
}

// round 10
// speedup vs baseline: 2.6509x; 1.2104x over previous
#include <cuda_runtime.h>
#include <cuda_bf16.h>
#include <cuda_fp16.h>
#include <math.h>
#include <stdint.h>

// Problem constants
#define N_TOK  8192
#define D_INF  1024
#define D_HIDF 4096
#define D_OUTF 1024
#define NE     8
#define TOPK   2
#define NROWS  (N_TOK * TOPK)

// ---------------- scratch (__device__ globals; allocation-free rule) --------
__device__ __align__(256) __half g_xhi[(size_t)N_TOK * D_INF];
__device__ __align__(256) __half g_xlo[(size_t)N_TOK * D_INF];
__device__ __align__(256) __half g_w1t[(size_t)NE * D_HIDF * D_INF];  // [E][Nhid][Kin]
__device__ __align__(256) __half g_w2t[(size_t)NE * D_OUTF * D_HIDF]; // [E][Nout][Khid]
__device__ __align__(256) __half g_hhi[(size_t)NROWS * D_HIDF];
__device__ __align__(256) __half g_hlo[(size_t)NROWS * D_HIDF];
__device__ __align__(256) float g_partial[(size_t)NROWS * D_OUTF];
__device__ int   g_counts[NE];
__device__ int   g_offsets[NE + 1];
__device__ int   g_cursor[NE];
__device__ int   g_row_token[NROWS];
__device__ int   g_token_row[NROWS];
__device__ int   g_e_of[NROWS];
__device__ float g_w_of[NROWS];

// ---------------- PTX helpers (base sm_103 only; NO 'a' features) -----------
__device__ __forceinline__ uint32_t smem_u32(const void* p) {
    uint32_t a;
    asm("{ .reg .u64 t; cvta.to.shared.u64 t, %1; cvt.u32.u64 %0, t; }"
        : "=r"(a) : "l"(p));
    return a;
}
__device__ __forceinline__ void cp16(uint32_t dst, const void* src) {
    unsigned long long g = (unsigned long long)__cvta_generic_to_global(src);
    asm volatile("cp.async.cg.shared.global [%0], [%1], 16;" :: "r"(dst), "l"(g));
}
#define CP_COMMIT() asm volatile("cp.async.commit_group;" ::: "memory")
template <int Np> __device__ __forceinline__ void cp_wait() {
    asm volatile("cp.async.wait_group %0;" :: "n"(Np) : "memory");
}
__device__ __forceinline__ void ldsm_x4(uint32_t& r0, uint32_t& r1, uint32_t& r2,
                                        uint32_t& r3, uint32_t addr) {
    asm volatile("ldmatrix.sync.aligned.m8n8.x4.shared.b16 {%0,%1,%2,%3}, [%4];"
                 : "=r"(r0), "=r"(r1), "=r"(r2), "=r"(r3) : "r"(addr));
}
__device__ __forceinline__ void mma_f16(float* c, const uint32_t* a, uint32_t b0,
                                        uint32_t b1) {
    asm volatile(
        "mma.sync.aligned.m16n8k16.row.col.f32.f16.f16.f32 "
        "{%0,%1,%2,%3}, {%4,%5,%6,%7}, {%8,%9}, {%0,%1,%2,%3};"
        : "+f"(c[0]), "+f"(c[1]), "+f"(c[2]), "+f"(c[3])
        : "r"(a[0]), "r"(a[1]), "r"(a[2]), "r"(a[3]), "r"(b0), "r"(b1));
}
__device__ __forceinline__ uint32_t hpack(__half a, __half b) {
    return (uint32_t)__half_as_ushort(a) | ((uint32_t)__half_as_ushort(b) << 16);
}

// ---------------- kernel 0: reset --------------------------------------------
__global__ void reset_kernel() {
    int t = threadIdx.x;
    if (t < NE) g_counts[t] = 0;
}

// ---------------- kernel 1: gating -------------------------------------------
__global__ __launch_bounds__(256) void gating_kernel(
    const float* __restrict__ x, const float* __restrict__ Wg,
    const float* __restrict__ bg)
{
    int gwarp = (blockIdx.x * blockDim.x + threadIdx.x) >> 5;
    int lane  = threadIdx.x & 31;
    if (gwarp >= N_TOK) return;
    const float* xr = x + (size_t)gwarp * D_INF;

    float acc[NE];
#pragma unroll
    for (int e = 0; e < NE; e++) acc[e] = 0.f;
    for (int k = lane; k < D_INF; k += 32) {
        float xv = xr[k];
        const float* wgr = Wg + (size_t)k * NE;
#pragma unroll
        for (int e = 0; e < NE; e++) acc[e] = fmaf(xv, wgr[e], acc[e]);
    }
#pragma unroll
    for (int off = 16; off; off >>= 1)
#pragma unroll
        for (int e = 0; e < NE; e++)
            acc[e] += __shfl_xor_sync(0xffffffffu, acc[e], off);

    if (lane == 0) {
        float s[NE];
#pragma unroll
        for (int e = 0; e < NE; e++) s[e] = acc[e] + bg[e];
        float mx = s[0];
#pragma unroll
        for (int e = 1; e < NE; e++) mx = fmaxf(mx, s[e]);
        float p[NE], sum = 0.f;
#pragma unroll
        for (int e = 0; e < NE; e++) { p[e] = expf(s[e] - mx); sum += p[e]; }
        float inv = 1.0f / sum;
#pragma unroll
        for (int e = 0; e < NE; e++) p[e] *= inv;
        int e0 = 0;
#pragma unroll
        for (int e = 1; e < NE; e++) if (s[e] > s[e0]) e0 = e;
        int e1 = (e0 == 0) ? 1 : 0;
#pragma unroll
        for (int e = 0; e < NE; e++) if (e != e0 && s[e] > s[e1]) e1 = e;
        float denom = p[e0] + p[e1] + 1e-8f;
        int n = gwarp;
        g_e_of[2*n+0] = e0;  g_e_of[2*n+1] = e1;
        g_w_of[2*n+0] = p[e0] / denom;  g_w_of[2*n+1] = p[e1] / denom;
        atomicAdd(&g_counts[e0], 1);
        atomicAdd(&g_counts[e1], 1);
    }
}

// ---------------- kernel 2/3: scan + placement -------------------------------
__global__ void scan_kernel() {
    int o = 0;
#pragma unroll
    for (int e = 0; e < NE; e++) { g_offsets[e] = o; g_cursor[e] = o; o += g_counts[e]; }
    g_offsets[NE] = o;
}
__global__ void place_kernel() {
    int n = blockIdx.x * blockDim.x + threadIdx.x;
    if (n >= N_TOK) return;
#pragma unroll
    for (int s = 0; s < TOPK; s++) {
        int e = g_e_of[2*n+s];
        int r = atomicAdd(&g_cursor[e], 1);
        g_row_token[r] = n;
        g_token_row[2*n+s] = r;
    }
}

// ---------------- prepass: x -> fp16 hi/lo -----------------------------------
__global__ __launch_bounds__(256) void cvtx_kernel(const float* __restrict__ x) {
    size_t i = ((size_t)blockIdx.x * 256 + threadIdx.x) * 4;
    float4 v = *(const float4*)(x + i);
    __half h0 = __float2half_rn(v.x), h1 = __float2half_rn(v.y);
    __half h2 = __float2half_rn(v.z), h3 = __float2half_rn(v.w);
    __half l0 = __float2half_rn(v.x - __half2float(h0));
    __half l1 = __float2half_rn(v.y - __half2float(h1));
    __half l2 = __float2half_rn(v.z - __half2float(h2));
    __half l3 = __float2half_rn(v.w - __half2float(h3));
    uint2 hh, ll;
    hh.x = hpack(h0, h1); hh.y = hpack(h2, h3);
    ll.x = hpack(l0, l1); ll.y = hpack(l2, l3);
    *(uint2*)(g_xhi + i) = hh;
    *(uint2*)(g_xlo + i) = ll;
}

// ---------------- prepass: W [E][K][N] -> WT fp16 [E][N][K] -------------------
template <int K, int N, int WCH>
__global__ void tpose_kernel(const float* __restrict__ Wsrc) {
    __shared__ float t[32][33];
    int e  = blockIdx.z;
    int n0 = blockIdx.x * 32, k0 = blockIdx.y * 32;
    int tx = threadIdx.x, ty = threadIdx.y;  // 32 x 8
    const float* src = Wsrc + ((size_t)e * K + k0) * N + n0;
#pragma unroll
    for (int i = 0; i < 4; i++)
        t[ty + 8*i][tx] = src[(size_t)(ty + 8*i) * N + tx];
    __syncthreads();
    __half* T = (WCH == 1) ? g_w1t : g_w2t;
    size_t ob = ((size_t)e * N + n0) * K + k0;
#pragma unroll
    for (int i = 0; i < 4; i++) {
        float v = t[tx][ty + 8*i];
        T[ob + (size_t)(ty + 8*i) * K + tx] = __float2half_rn(v);
    }
}

// ---------------- grouped HMMA GEMM (fp16 hi/lo 2-pass) -----------------------
// BM=128, BN=128, BK=64, 256 threads (8 warps, warp tile 64x32), 2-stage
// cp.async, 2 CTAs/SM. Stage rows: [0,128)=Ahi, [128,256)=Alo, [256,384)=B.
#define ROWP       144
#define STAGE_ROWS 384
#define STAGE_SZ   (STAGE_ROWS * ROWP)      // 55296
#define SMEM_DYN   (2 * STAGE_SZ + 128)     // 110720

template <int G>
__global__ __launch_bounds__(256, 2) void gemm_kernel(const float* __restrict__ bias_g) {
    constexpr int KD = (G == 1) ? D_INF : D_HIDF;
    constexpr int NT = (G == 1) ? D_HIDF : D_OUTF;
    constexpr int KT = KD / 64;

    const int e    = blockIdx.z;
    const int rbeg = g_offsets[e];
    const int rend = g_offsets[e + 1];
    const int m0   = rbeg + blockIdx.y * 128;
    if (m0 >= rend) return;
    const int n0   = blockIdx.x * 128;

    __shared__ float sbias[128];
    extern __shared__ char dsm[];
    const uint32_t dynb = (smem_u32(dsm) + 127u) & ~127u;

    const int tid  = threadIdx.x;
    const int wid  = tid >> 5;
    const int lane = tid & 31;

    if (tid < 128) sbias[tid] = bias_g[(size_t)e * NT + n0 + tid];

    const __half* ahi_g = (G == 1) ? g_xhi : g_hhi;
    const __half* alo_g = (G == 1) ? g_xlo : g_hlo;
    const __half* b_g   = (G == 1) ? g_w1t : g_w2t;

    // ---- loader geometry: 384 rows / 256 threads (row tid, + row 256+tid for tid<128)
    const __half* gsrc[2];
    uint32_t dstoff[2];
    const bool has2 = (tid < 128);
#pragma unroll
    for (int q = 0; q < 2; q++) {
        const int r = tid + 256 * q;        // q0: 0..255, q1: 256..383 (tid<128)
        if (r < 256) {                      // A rows (hi then lo)
            int gr = m0 + (r & 127);
            if (gr >= rend) gr = rbeg;      // valid garbage row; epilogue masks
            size_t rowb = (G == 1) ? (size_t)g_row_token[gr] * KD : (size_t)gr * KD;
            gsrc[q] = ((r < 128) ? ahi_g : alo_g) + rowb;
            dstoff[q] = (uint32_t)(r * ROWP);
        } else if (r < 384) {               // B rows
            const int br = r - 256;         // 0..127
            size_t rowb = ((size_t)e * NT + n0 + br) * KD;
            gsrc[q] = b_g + rowb;
            dstoff[q] = (uint32_t)(r * ROWP);
        } else {
            gsrc[q] = gsrc[0];              // unused (guarded by has2)
            dstoff[q] = dstoff[0];
        }
    }

    auto load_stage = [&](int kt, int stg) {
        const uint32_t sb = dynb + (uint32_t)stg * STAGE_SZ;
        const int k0 = kt * 64;
        {
            const __half* src = gsrc[0] + k0;
            const uint32_t dst = sb + dstoff[0];
#pragma unroll
            for (int c = 0; c < 8; c++) cp16(dst + c * 16, src + c * 8);
        }
        if (has2) {
            const __half* src = gsrc[1] + k0;
            const uint32_t dst = sb + dstoff[1];
#pragma unroll
            for (int c = 0; c < 8; c++) cp16(dst + c * 16, src + c * 8);
        }
        CP_COMMIT();
    };

    // ---- fragment address bases ----
    const int wm = (wid >> 2) * 64;     // warp M offset: 0,64
    const int wn = (wid & 3) * 32;      // warp N offset: 0,32,64,96
    const int mtx = lane >> 3;          // ldmatrix matrix id 0..3
    const int inr = lane & 7;
    // A x4 tile: matrices {m0-7 k0, m8-15 k0, m0-7 k8, m8-15 k8}
    const uint32_t aoff_hi = (uint32_t)((wm + (mtx & 1) * 8 + inr) * ROWP + (mtx >> 1) * 16);
    const uint32_t aoff_lo = aoff_hi + 128 * ROWP;
    // B x4 tile: matrices {n0-7 k0, n0-7 k8, n8-15 k0, n8-15 k8}
    const uint32_t boff = (uint32_t)((256 + wn + (mtx >> 1) * 8 + inr) * ROWP + (mtx & 1) * 16);

    float acc[4][4][4];
#pragma unroll
    for (int i = 0; i < 4; i++)
#pragma unroll
        for (int j = 0; j < 4; j++)
#pragma unroll
            for (int q = 0; q < 4; q++) acc[i][j][q] = 0.f;

    load_stage(0, 0);

    for (int kt = 0; kt < KT; kt++) {
        cp_wait<0>();
        __syncthreads();   // stage kt visible; prior stage's consumers done
        if (kt + 1 < KT) load_stage(kt + 1, (kt + 1) & 1);

        const uint32_t sb = dynb + (uint32_t)(kt & 1) * STAGE_SZ;
#pragma unroll
        for (int ks = 0; ks < 4; ks++) {
            uint32_t ah[4][4], al[4][4], bh[2][4];
#pragma unroll
            for (int mt = 0; mt < 4; mt++) {
                const uint32_t ao = (uint32_t)(mt * 16 * ROWP + ks * 32);
                ldsm_x4(ah[mt][0], ah[mt][1], ah[mt][2], ah[mt][3], sb + aoff_hi + ao);
                ldsm_x4(al[mt][0], al[mt][1], al[mt][2], al[mt][3], sb + aoff_lo + ao);
            }
#pragma unroll
            for (int np = 0; np < 2; np++) {
                const uint32_t go = (uint32_t)(np * 16 * ROWP + ks * 32);
                ldsm_x4(bh[np][0], bh[np][1], bh[np][2], bh[np][3], sb + boff + go);
            }
            // hi pass over all accumulators, then lo pass (RAW distance 8)
#pragma unroll
            for (int np = 0; np < 2; np++)
#pragma unroll
                for (int mt = 0; mt < 4; mt++) {
                    mma_f16(acc[mt][2*np+0], ah[mt], bh[np][0], bh[np][1]);
                    mma_f16(acc[mt][2*np+1], ah[mt], bh[np][2], bh[np][3]);
                }
#pragma unroll
            for (int np = 0; np < 2; np++)
#pragma unroll
                for (int mt = 0; mt < 4; mt++) {
                    mma_f16(acc[mt][2*np+0], al[mt], bh[np][0], bh[np][1]);
                    mma_f16(acc[mt][2*np+1], al[mt], bh[np][2], bh[np][3]);
                }
        }
    }

    // ---- epilogue ----
    const int erow = m0 + wm + (lane >> 2);
    const int ecol = n0 + wn + 2 * (lane & 3);
#pragma unroll
    for (int mt = 0; mt < 4; mt++) {
#pragma unroll
        for (int nt = 0; nt < 4; nt++) {
            const int col = ecol + nt * 8;
            const float bs0 = sbias[col - n0], bs1 = sbias[col - n0 + 1];
#pragma unroll
            for (int hrow = 0; hrow < 2; hrow++) {
                const int row = erow + mt * 16 + hrow * 8;
                if (row < rend) {
                    float v0 = acc[mt][nt][2 * hrow + 0] + bs0;
                    float v1 = acc[mt][nt][2 * hrow + 1] + bs1;
                    size_t off = (size_t)row * NT + col;
                    if (G == 1) {
                        v0 = fmaxf(v0, 0.f);
                        v1 = fmaxf(v1, 0.f);
                        __half h0 = __float2half_rn(v0);
                        __half h1 = __float2half_rn(v1);
                        __half l0 = __float2half_rn(v0 - __half2float(h0));
                        __half l1 = __float2half_rn(v1 - __half2float(h1));
                        *(uint32_t*)(g_hhi + off) = hpack(h0, h1);
                        *(uint32_t*)(g_hlo + off) = hpack(l0, l1);
                    } else {
                        float2 o; o.x = v0; o.y = v1;
                        *(float2*)(g_partial + off) = o;
                    }
                }
            }
        }
    }
}

// ---------------- combine -----------------------------------------------------
__global__ __launch_bounds__(256) void combine_kernel(float* __restrict__ out) {
    int idx = blockIdx.x * blockDim.x + threadIdx.x;
    int n = idx >> 8;
    int cc = (idx & 255) << 2;
    if (n >= N_TOK) return;
    float w0 = g_w_of[2*n+0], w1 = g_w_of[2*n+1];
    int   r0 = g_token_row[2*n+0], r1 = g_token_row[2*n+1];
    float4 p0 = *(const float4*)(g_partial + (size_t)r0 * D_OUTF + cc);
    float4 p1 = *(const float4*)(g_partial + (size_t)r1 * D_OUTF + cc);
    float4 o;
    o.x = w0*p0.x + w1*p1.x;  o.y = w0*p0.y + w1*p1.y;
    o.z = w0*p0.z + w1*p1.z;  o.w = w0*p0.w + w1*p1.w;
    *(float4*)(out + (size_t)n * D_OUTF + cc) = o;
}

// ---------------- launcher ----------------------------------------------------
extern "C" void kernel_launch(void* const* d_in, const int* in_sizes, int n_in,
                              void* d_out, int out_size) {
    const float* x  = (const float*)d_in[0];
    const float* W1 = (const float*)d_in[1];
    const float* b1 = (const float*)d_in[2];
    const float* W2 = (const float*)d_in[3];
    const float* b2 = (const float*)d_in[4];
    const float* Wg = (const float*)d_in[5];
    const float* bg = (const float*)d_in[6];
    float* out = (float*)d_out;

    cudaFuncSetAttribute(gemm_kernel<1>, cudaFuncAttributeMaxDynamicSharedMemorySize, SMEM_DYN);
    cudaFuncSetAttribute(gemm_kernel<2>, cudaFuncAttributeMaxDynamicSharedMemorySize, SMEM_DYN);

    reset_kernel<<<1, 32>>>();
    gating_kernel<<<N_TOK / 8, 256>>>(x, Wg, bg);
    scan_kernel<<<1, 1>>>();
    place_kernel<<<N_TOK / 256, 256>>>();

    cvtx_kernel<<<(N_TOK * D_INF / 4) / 256, 256>>>(x);
    tpose_kernel<D_INF,  D_HIDF, 1><<<dim3(D_HIDF/32, D_INF/32,  NE), dim3(32, 8)>>>(W1);
    tpose_kernel<D_HIDF, D_OUTF, 2><<<dim3(D_OUTF/32, D_HIDF/32, NE), dim3(32, 8)>>>(W2);

    gemm_kernel<1><<<dim3(D_HIDF/128, 64, NE), 256, SMEM_DYN>>>(b1);
    gemm_kernel<2><<<dim3(D_OUTF/128, 64, NE), 256, SMEM_DYN>>>(b2);

    combine_kernel<<<(N_TOK * D_OUTF / 4) / 256, 256>>>(out);
}